// round 1
// baseline (speedup 1.0000x reference)
#include <cuda_runtime.h>
#include <math.h>

// Problem constants
#define BATCH 8
#define LSEQ  2048
#define DDIM  1024
#define NEGF  (-1e30f)

// ---------------- scratch (device globals; no allocation allowed) ----------------
__device__ float g_Q  [(size_t)BATCH * LSEQ * DDIM];   // [b, L1, D]
__device__ float g_K  [(size_t)BATCH * LSEQ * DDIM];   // [b, L2, D]
__device__ float g_V1T[(size_t)BATCH * DDIM * LSEQ];   // [b, D, L1]
__device__ float g_V2T[(size_t)BATCH * DDIM * LSEQ];   // [b, D, L2]
__device__ float g_XmT[(size_t)BATCH * DDIM * LSEQ];   // [b, D, L2]  (x1_mid^T)
__device__ float g_S  [(size_t)BATCH * LSEQ * LSEQ];   // logits, then A2 in-place
__device__ float g_A1T[(size_t)BATCH * LSEQ * LSEQ];   // [b, L2, L1]
__device__ float g_cmax[BATCH * LSEQ];
__device__ float g_crcp[BATCH * LSEQ];

__device__ __forceinline__ float to_tf32(float x) {
    unsigned u;
    asm("cvt.rna.tf32.f32 %0, %1;" : "=r"(u) : "f"(x));
    return __uint_as_float(u);
}

#define MMA_TF32(d, a, b)                                                  \
    asm volatile(                                                          \
        "mma.sync.aligned.m16n8k8.row.col.f32.tf32.tf32.f32 "              \
        "{%0,%1,%2,%3}, {%4,%5,%6,%7}, {%8,%9}, {%0,%1,%2,%3};"            \
        : "+f"(d[0]), "+f"(d[1]), "+f"(d[2]), "+f"(d[3])                   \
        : "r"(a[0]), "r"(a[1]), "r"(a[2]), "r"(a[3]), "r"(b[0]), "r"(b[1]))

// ---------------------------------------------------------------------------
// Generic batched NT GEMM: C[m,n] = sum_k A[m,k] * B[n,k]  (tf32 tensor cores)
// A: [M,K] row-major per batch (stride sA), B: [N,K] row-major (stride sB).
// Tile 128x128x16, 256 threads, 8 warps as 4(m) x 2(n), warp tile 32x64.
// MODE 0: +bias[n], normal store C[m,n] (ldc=N)
// MODE 1: +bias[n], TRANSPOSED store C[n,m] (ld=M) via smem staging
// MODE 2: *scale + (1-mask[z,n])*NEG, normal store
// MODE 3: plain normal store
// MODE 4: *mask[z,m], TRANSPOSED store C[n,m]
// Requires M%128==0, N%128==0, K%16==0 (true for all our shapes).
// ---------------------------------------------------------------------------
template <int MODE>
__global__ __launch_bounds__(256)
void gemm_nt(const float* __restrict__ A, const float* __restrict__ B,
             float* __restrict__ C, int M, int N, int K,
             long long sA, long long sB, long long sC,
             const float* __restrict__ bias,
             const float* __restrict__ mask, float scale)
{
    __shared__ float sh[10240];  // As: [2][128][20] @0, Bs: [2][128][20] @5120; epilogue reuses as Csh[128][65]

    const int z  = blockIdx.z;
    const int m0 = blockIdx.y * 128;
    const int n0 = blockIdx.x * 128;
    const int tid  = threadIdx.x;
    const int warp = tid >> 5, lane = tid & 31;
    const int wm = warp & 3, wn = warp >> 2;
    const int g  = lane >> 2, tg = lane & 3;
    const int lr = tid >> 2;          // 0..63
    const int lc = (tid & 3) << 2;    // 0,4,8,12

    const float* Ag = A + (long long)z * sA + (long long)(m0 + lr) * K + lc;
    const float* Bg = B + (long long)z * sB + (long long)(n0 + lr) * K + lc;

    float acc[2][8][4];
#pragma unroll
    for (int a = 0; a < 2; a++)
#pragma unroll
        for (int b = 0; b < 8; b++)
#pragma unroll
            for (int c = 0; c < 4; c++) acc[a][b][c] = 0.0f;

    float4 ra0, ra1, rb0, rb1;

    // prologue: load tile 0 and stage
    ra0 = *(const float4*)(Ag);
    ra1 = *(const float4*)(Ag + (long long)64 * K);
    rb0 = *(const float4*)(Bg);
    rb1 = *(const float4*)(Bg + (long long)64 * K);
    {
        float* As = sh;
        float* Bs = sh + 5120;
        *(float4*)(As + lr * 20 + lc)        = make_float4(to_tf32(ra0.x), to_tf32(ra0.y), to_tf32(ra0.z), to_tf32(ra0.w));
        *(float4*)(As + (lr + 64) * 20 + lc) = make_float4(to_tf32(ra1.x), to_tf32(ra1.y), to_tf32(ra1.z), to_tf32(ra1.w));
        *(float4*)(Bs + lr * 20 + lc)        = make_float4(to_tf32(rb0.x), to_tf32(rb0.y), to_tf32(rb0.z), to_tf32(rb0.w));
        *(float4*)(Bs + (lr + 64) * 20 + lc) = make_float4(to_tf32(rb1.x), to_tf32(rb1.y), to_tf32(rb1.z), to_tf32(rb1.w));
    }
    __syncthreads();

    const int KT = K >> 4;
    int buf = 0;
    for (int kt = 0; kt < KT; ++kt) {
        if (kt + 1 < KT) {
            const int off = (kt + 1) << 4;
            ra0 = *(const float4*)(Ag + off);
            ra1 = *(const float4*)(Ag + (long long)64 * K + off);
            rb0 = *(const float4*)(Bg + off);
            rb1 = *(const float4*)(Bg + (long long)64 * K + off);
        }
        {
            const float* As = sh + buf * 2560;
            const float* Bs = sh + 5120 + buf * 2560;
#pragma unroll
            for (int ks = 0; ks < 2; ++ks) {
                const int k0 = ks * 8 + tg;
                unsigned af[2][4], bf[8][2];
#pragma unroll
                for (int mt = 0; mt < 2; ++mt) {
                    const int mb = wm * 32 + mt * 16 + g;
                    af[mt][0] = __float_as_uint(As[mb * 20 + k0]);
                    af[mt][1] = __float_as_uint(As[(mb + 8) * 20 + k0]);
                    af[mt][2] = __float_as_uint(As[mb * 20 + k0 + 4]);
                    af[mt][3] = __float_as_uint(As[(mb + 8) * 20 + k0 + 4]);
                }
#pragma unroll
                for (int nt = 0; nt < 8; ++nt) {
                    const int nb = wn * 64 + nt * 8 + g;
                    bf[nt][0] = __float_as_uint(Bs[nb * 20 + k0]);
                    bf[nt][1] = __float_as_uint(Bs[nb * 20 + k0 + 4]);
                }
#pragma unroll
                for (int mt = 0; mt < 2; ++mt)
#pragma unroll
                    for (int nt = 0; nt < 8; ++nt)
                        MMA_TF32(acc[mt][nt], af[mt], bf[nt]);
            }
        }
        if (kt + 1 < KT) {
            float* As = sh + (buf ^ 1) * 2560;
            float* Bs = sh + 5120 + (buf ^ 1) * 2560;
            *(float4*)(As + lr * 20 + lc)        = make_float4(to_tf32(ra0.x), to_tf32(ra0.y), to_tf32(ra0.z), to_tf32(ra0.w));
            *(float4*)(As + (lr + 64) * 20 + lc) = make_float4(to_tf32(ra1.x), to_tf32(ra1.y), to_tf32(ra1.z), to_tf32(ra1.w));
            *(float4*)(Bs + lr * 20 + lc)        = make_float4(to_tf32(rb0.x), to_tf32(rb0.y), to_tf32(rb0.z), to_tf32(rb0.w));
            *(float4*)(Bs + (lr + 64) * 20 + lc) = make_float4(to_tf32(rb1.x), to_tf32(rb1.y), to_tf32(rb1.z), to_tf32(rb1.w));
        }
        __syncthreads();
        buf ^= 1;
    }

    // ---------------- epilogue ----------------
    if (MODE == 0 || MODE == 2 || MODE == 3) {
        float* Cb = C + (long long)z * sC;
#pragma unroll
        for (int mt = 0; mt < 2; ++mt) {
#pragma unroll
            for (int nt = 0; nt < 8; ++nt) {
                const int mA = m0 + wm * 32 + mt * 16 + g;
                const int n  = n0 + wn * 64 + nt * 8 + tg * 2;
                float v0 = acc[mt][nt][0], v1 = acc[mt][nt][1];
                float v2 = acc[mt][nt][2], v3 = acc[mt][nt][3];
                if (MODE == 0) {
                    const float b0 = bias[n], b1 = bias[n + 1];
                    v0 += b0; v1 += b1; v2 += b0; v3 += b1;
                }
                if (MODE == 2) {
                    const float mb0 = (1.0f - mask[(long long)z * N + n]) * NEGF;
                    const float mb1 = (1.0f - mask[(long long)z * N + n + 1]) * NEGF;
                    v0 = v0 * scale + mb0; v1 = v1 * scale + mb1;
                    v2 = v2 * scale + mb0; v3 = v3 * scale + mb1;
                }
                *(float2*)(Cb + (long long)mA * N + n)       = make_float2(v0, v1);
                *(float2*)(Cb + (long long)(mA + 8) * N + n) = make_float2(v2, v3);
            }
        }
    } else {
        // transposed store via smem staging (two 64-col chunks)
        float* Csh = sh;
#pragma unroll
        for (int ch = 0; ch < 2; ++ch) {
            __syncthreads();
            if (wn == ch) {
#pragma unroll
                for (int mt = 0; mt < 2; ++mt) {
#pragma unroll
                    for (int nt = 0; nt < 8; ++nt) {
                        const int ml = wm * 32 + mt * 16 + g;
                        const int nl = nt * 8 + tg * 2;
                        float v0 = acc[mt][nt][0], v1 = acc[mt][nt][1];
                        float v2 = acc[mt][nt][2], v3 = acc[mt][nt][3];
                        if (MODE == 1) {
                            const float b0 = bias[n0 + ch * 64 + nl];
                            const float b1 = bias[n0 + ch * 64 + nl + 1];
                            v0 += b0; v1 += b1; v2 += b0; v3 += b1;
                        }
                        if (MODE == 4) {
                            const float mk0 = mask[(long long)z * M + m0 + ml];
                            const float mk1 = mask[(long long)z * M + m0 + ml + 8];
                            v0 *= mk0; v1 *= mk0; v2 *= mk1; v3 *= mk1;
                        }
                        Csh[ml * 65 + nl]           = v0;
                        Csh[ml * 65 + nl + 1]       = v1;
                        Csh[(ml + 8) * 65 + nl]     = v2;
                        Csh[(ml + 8) * 65 + nl + 1] = v3;
                    }
                }
            }
            __syncthreads();
#pragma unroll
            for (int i = 0; i < 32; ++i) {
                const int idx = tid + i * 256;
                const int nl = idx >> 7;
                const int ml = idx & 127;
                C[(long long)z * sC + (long long)(n0 + ch * 64 + nl) * M + (m0 + ml)] =
                    Csh[ml * 65 + nl];
            }
        }
    }
}

// ---------------- softmax helpers ----------------

// per-column (axis L1) max & 1/sum over S[b, :, m]
__global__ __launch_bounds__(256)
void colstats_k(const float* __restrict__ S, float* __restrict__ cmax, float* __restrict__ crcp)
{
    const int z = blockIdx.y;
    const int m = blockIdx.x * 256 + threadIdx.x;
    const float* p = S + (long long)z * LSEQ * LSEQ + m;
    float mx = -3.4e38f;
#pragma unroll 4
    for (int l = 0; l < LSEQ; ++l) mx = fmaxf(mx, p[(long long)l * LSEQ]);
    float sm = 0.0f;
#pragma unroll 4
    for (int l = 0; l < LSEQ; ++l) sm += expf(p[(long long)l * LSEQ] - mx);
    cmax[z * LSEQ + m] = mx;
    crcp[z * LSEQ + m] = 1.0f / sm;
}

// A1T[b, m, l] = exp(S[b,l,m] - cmax[b,m]) * crcp[b,m]   (32x32 tiled transpose)
__global__ __launch_bounds__(256)
void a1t_k(const float* __restrict__ S, float* __restrict__ A1T,
           const float* __restrict__ cmax, const float* __restrict__ crcp)
{
    __shared__ float t[32][33];
    const int z = blockIdx.z;
    const int x0 = blockIdx.x * 32;  // m (L2)
    const int y0 = blockIdx.y * 32;  // l (L1)
    const int tx = threadIdx.x, ty = threadIdx.y;
    const float* Sb = S + (long long)z * LSEQ * LSEQ;
#pragma unroll
    for (int r = 0; r < 4; ++r)
        t[ty + r * 8][tx] = Sb[(long long)(y0 + ty + r * 8) * LSEQ + x0 + tx];
    __syncthreads();
#pragma unroll
    for (int r = 0; r < 4; ++r) {
        const int m = x0 + ty + r * 8;
        const int l = y0 + tx;
        const float v = t[tx][ty + r * 8];
        A1T[(long long)z * LSEQ * LSEQ + (long long)m * LSEQ + l] =
            expf(v - cmax[z * LSEQ + m]) * crcp[z * LSEQ + m];
    }
}

// in-place row softmax over L2: S[b,l,:] -> A2
__global__ __launch_bounds__(256)
void row_softmax_k(float* __restrict__ S)
{
    __shared__ float sred[8];
    const long long row = blockIdx.x;
    float* p = S + row * LSEQ;
    const int tid = threadIdx.x;
    float v[8];
#pragma unroll
    for (int i = 0; i < 8; ++i) v[i] = p[tid + i * 256];

    float mx = v[0];
#pragma unroll
    for (int i = 1; i < 8; ++i) mx = fmaxf(mx, v[i]);
#pragma unroll
    for (int o = 16; o; o >>= 1) mx = fmaxf(mx, __shfl_xor_sync(0xffffffffu, mx, o));
    if ((tid & 31) == 0) sred[tid >> 5] = mx;
    __syncthreads();
    float m2 = sred[0];
#pragma unroll
    for (int j = 1; j < 8; ++j) m2 = fmaxf(m2, sred[j]);
    __syncthreads();

    float sm = 0.0f;
#pragma unroll
    for (int i = 0; i < 8; ++i) { v[i] = expf(v[i] - m2); sm += v[i]; }
#pragma unroll
    for (int o = 16; o; o >>= 1) sm += __shfl_xor_sync(0xffffffffu, sm, o);
    if ((tid & 31) == 0) sred[tid >> 5] = sm;
    __syncthreads();
    float s2 = 0.0f;
#pragma unroll
    for (int j = 0; j < 8; ++j) s2 += sred[j];
    const float r = 1.0f / s2;
#pragma unroll
    for (int i = 0; i < 8; ++i) p[tid + i * 256] = v[i] * r;
}

// ---------------- launcher ----------------
extern "C" void kernel_launch(void* const* d_in, const int* in_sizes, int n_in,
                              void* d_out, int out_size)
{
    const float* x1   = (const float*)d_in[0];
    const float* x2   = (const float*)d_in[1];
    const float* mask = (const float*)d_in[2];
    const float* Wq   = (const float*)d_in[3];
    const float* bq   = (const float*)d_in[4];
    const float* Wk   = (const float*)d_in[5];
    const float* bk   = (const float*)d_in[6];
    const float* Wv   = (const float*)d_in[7];
    const float* bv   = (const float*)d_in[8];

    float* out1 = (float*)d_out;                                      // x1_out
    float* out2 = out1 + (long long)BATCH * LSEQ * DDIM;              // x2_out

    float *Q, *Kb, *V1T, *V2T, *XmT, *S, *A1T, *cmax, *crcp;
    cudaGetSymbolAddress((void**)&Q,   g_Q);
    cudaGetSymbolAddress((void**)&Kb,  g_K);
    cudaGetSymbolAddress((void**)&V1T, g_V1T);
    cudaGetSymbolAddress((void**)&V2T, g_V2T);
    cudaGetSymbolAddress((void**)&XmT, g_XmT);
    cudaGetSymbolAddress((void**)&S,   g_S);
    cudaGetSymbolAddress((void**)&A1T, g_A1T);
    cudaGetSymbolAddress((void**)&cmax, g_cmax);
    cudaGetSymbolAddress((void**)&crcp, g_crcp);

    const long long sX  = (long long)LSEQ * DDIM;   // per-batch x / q / k stride
    const long long sT  = (long long)DDIM * LSEQ;   // per-batch transposed stride
    const long long sS  = (long long)LSEQ * LSEQ;   // per-batch logits stride
    const float scale = 0.03125f;                   // 1/sqrt(1024)

    dim3 blk(256);
    dim3 gProj(DDIM / 128, LSEQ / 128, BATCH);      // (8,16,8)
    dim3 gS(LSEQ / 128, LSEQ / 128, BATCH);         // (16,16,8)

    // projections
    gemm_nt<0><<<gProj, blk>>>(x1, Wq, Q,   LSEQ, DDIM, DDIM, sX, 0, sX, bq, nullptr, 0.f);
    gemm_nt<0><<<gProj, blk>>>(x2, Wk, Kb,  LSEQ, DDIM, DDIM, sX, 0, sX, bk, nullptr, 0.f);
    gemm_nt<1><<<gProj, blk>>>(x1, Wv, V1T, LSEQ, DDIM, DDIM, sX, 0, sT, bv, nullptr, 0.f);
    gemm_nt<1><<<gProj, blk>>>(x2, Wv, V2T, LSEQ, DDIM, DDIM, sX, 0, sT, bv, nullptr, 0.f);

    // logits with scale + additive mask
    gemm_nt<2><<<gS, blk>>>(Q, Kb, S, LSEQ, LSEQ, DDIM, sX, sX, sS, nullptr, mask, scale);

    // softmaxes
    colstats_k<<<dim3(LSEQ / 256, BATCH), blk>>>(S, cmax, crcp);
    a1t_k<<<dim3(LSEQ / 32, LSEQ / 32, BATCH), dim3(32, 8)>>>(S, A1T, cmax, crcp);
    row_softmax_k<<<BATCH * LSEQ, blk>>>(S);   // S becomes A2 in place

    // x2_out = A2 @ V2
    gemm_nt<3><<<gProj, blk>>>(S, V2T, out2, LSEQ, DDIM, LSEQ, sS, sT, sX, nullptr, nullptr, 0.f);
    // x1_mid^T = (A1^T @ V1) * mask, stored [D, L2]
    gemm_nt<4><<<gProj, blk>>>(A1T, V1T, XmT, LSEQ, DDIM, LSEQ, sS, sT, sT, nullptr, mask, 0.f);
    // x1_out = A2 @ x1_mid
    gemm_nt<3><<<gProj, blk>>>(S, XmT, out1, LSEQ, DDIM, LSEQ, sS, sT, sX, nullptr, nullptr, 0.f);
}

// round 6
// speedup vs baseline: 1.2462x; 1.2462x over previous
#include <cuda_runtime.h>
#include <math.h>
#include <stdint.h>

// Problem constants
#define BATCH 8
#define LSEQ  2048
#define DDIM  1024
#define NEGF  (-1e30f)

// GEMM tiling: CTA 128(M) x 256(N) x 32(K), 8 warps as 2(m) x 4(n), warp tile 64x64
#define NTHREADS 256
#define STAGES 3
#define STRIDE 36                       // smem row stride in words (conflict-free: bank=4g+tg)
#define A_WORDS (128 * STRIDE)          // 4608
#define B_WORDS (256 * STRIDE)          // 9216
#define STAGE_WORDS (A_WORDS + B_WORDS) // 13824
#define STAGE_BYTES (STAGE_WORDS * 4)   // 55296
#define A_BYTES (A_WORDS * 4)           // 18432
#define SMEM_TOTAL (STAGES * STAGE_BYTES) // 165888

// ---------------- scratch (device globals; no allocation allowed) ----------------
__device__ float g_Q  [(size_t)BATCH * LSEQ * DDIM];
__device__ float g_K  [(size_t)BATCH * LSEQ * DDIM];
__device__ float g_V1T[(size_t)BATCH * DDIM * LSEQ];
__device__ float g_V2T[(size_t)BATCH * DDIM * LSEQ];
__device__ float g_XmT[(size_t)BATCH * DDIM * LSEQ];
__device__ float g_S  [(size_t)BATCH * LSEQ * LSEQ];
__device__ float g_A1T[(size_t)BATCH * LSEQ * LSEQ];
__device__ float g_cmax[BATCH * LSEQ];
__device__ float g_crcp[BATCH * LSEQ];
__device__ float g_x1r[(size_t)BATCH * LSEQ * DDIM];
__device__ float g_x2r[(size_t)BATCH * LSEQ * DDIM];
__device__ float g_Wqr[(size_t)DDIM * DDIM];
__device__ float g_Wkr[(size_t)DDIM * DDIM];
__device__ float g_Wvr[(size_t)DDIM * DDIM];

// ---------------- helpers ----------------
__device__ __forceinline__ float to_tf32(float x) {
    unsigned u;
    asm("cvt.rna.tf32.f32 %0, %1;" : "=r"(u) : "f"(x));
    return __uint_as_float(u);
}

__device__ __forceinline__ uint32_t smem_to_u32(const void* p) {
    uint32_t a;
    asm("{ .reg .u64 t; cvta.to.shared.u64 t, %1; cvt.u32.u64 %0, t; }" : "=r"(a) : "l"(p));
    return a;
}

#define CP_ASYNC16(dst, src) \
    asm volatile("cp.async.cg.shared.global [%0], [%1], 16;" :: "r"(dst), "l"(src) : "memory")
#define CP_COMMIT() asm volatile("cp.async.commit_group;" ::: "memory")

#define MMA_TF32(d, a, b)                                                  \
    asm volatile(                                                          \
        "mma.sync.aligned.m16n8k8.row.col.f32.tf32.tf32.f32 "              \
        "{%0,%1,%2,%3}, {%4,%5,%6,%7}, {%8,%9}, {%0,%1,%2,%3};"            \
        : "+f"(d[0]), "+f"(d[1]), "+f"(d[2]), "+f"(d[3])                   \
        : "r"(a[0]), "r"(a[1]), "r"(a[2]), "r"(a[3]), "r"(b[0]), "r"(b[1]))

// ---------------------------------------------------------------------------
// Batched NT GEMM: C[m,n] = sum_k A[m,k]*B[n,k]   (tf32 mma.sync, cp.async pipe)
// Inputs must be tf32-exact fp32 (pre-rounded); no in-loop conversion needed.
// MODE 0: +bias[n], round tf32, normal store
// MODE 1: +bias[n], round tf32, transposed store C[n,m]
// MODE 2: *scale + (1-mask[z,n])*NEG, normal store (no round)
// MODE 3: plain normal store (no round)
// MODE 4: *mask[z,m], round tf32, transposed store C[n,m]
// Requires M%128==0, N%256==0, K%32==0.
// ---------------------------------------------------------------------------
template <int MODE>
__global__ __launch_bounds__(NTHREADS, 1)
void gemm_tc(const float* __restrict__ A, const float* __restrict__ B, float* __restrict__ C,
             int M, int N, int K, long long sA, long long sB, long long sC,
             const float* __restrict__ bias, const float* __restrict__ mask, float scale)
{
    extern __shared__ float sh[];
    const uint32_t smem_u = smem_to_u32(sh);
    const int tid = threadIdx.x, wid = tid >> 5, lane = tid & 31;
    const int wm = wid & 1, wn = wid >> 1;      // 2 x 4 warps
    const int g = lane >> 2, tg = lane & 3;
    const int z = blockIdx.z;
    const int m0 = blockIdx.y * 128;
    const int n0 = blockIdx.x * 256;

    const float* Abase = A + (long long)z * sA + (long long)m0 * K;
    const float* Bbase = B + (long long)z * sB + (long long)n0 * K;
    const int T = K >> 5;

    // cp.async staging: A 128 rows x 32 cols, B 256 rows x 32 cols, 16B chunks
    const int sr_a = tid >> 3;          // row within 128 per iter-chunk of 256 threads
    const int sq = (tid & 7) << 2;      // col word 0,4,...,28
    auto stage = [&](int u) {
        const int s = u % STAGES;
        const uint32_t sa = smem_u + s * STAGE_BYTES;
        const uint32_t sb = sa + A_BYTES;
        const float* Asrc = Abase + (size_t)u * 32 + sq;
        const float* Bsrc = Bbase + (size_t)u * 32 + sq;
        const uint32_t doff = sq * 4;
#pragma unroll
        for (int i = 0; i < 4; ++i) {
            const int r = sr_a + i * 32;
            CP_ASYNC16(sa + r * (STRIDE * 4) + doff, Asrc + (size_t)r * K);
        }
#pragma unroll
        for (int i = 0; i < 8; ++i) {
            const int r = sr_a + i * 32;
            CP_ASYNC16(sb + r * (STRIDE * 4) + doff, Bsrc + (size_t)r * K);
        }
        CP_COMMIT();
    };

    float acc[4][8][4];
#pragma unroll
    for (int a = 0; a < 4; ++a)
#pragma unroll
        for (int b = 0; b < 8; ++b)
#pragma unroll
            for (int c = 0; c < 4; ++c) acc[a][b][c] = 0.0f;

    stage(0);
    stage(1);

    const int arow0 = (wm * 64 + g) * STRIDE;
    const int brow0 = (wn * 64 + g) * STRIDE;

    for (int t = 0; t < T; ++t) {
        if (t < T - 1) asm volatile("cp.async.wait_group 1;" ::: "memory");
        else           asm volatile("cp.async.wait_group 0;" ::: "memory");
        __syncthreads();

        if (t + 2 < T) stage(t + 2);

        const float* As = sh + (t % STAGES) * STAGE_WORDS;
        const float* Bs = As + A_WORDS;
#pragma unroll
        for (int ks = 0; ks < 4; ++ks) {
            const int k0 = ks * 8 + tg;
            unsigned af[4][4], bf[8][2];
#pragma unroll
            for (int mt = 0; mt < 4; ++mt) {
                const int rb = arow0 + mt * (16 * STRIDE) + k0;
                af[mt][0] = __float_as_uint(As[rb]);
                af[mt][1] = __float_as_uint(As[rb + 8 * STRIDE]);
                af[mt][2] = __float_as_uint(As[rb + 4]);
                af[mt][3] = __float_as_uint(As[rb + 8 * STRIDE + 4]);
            }
#pragma unroll
            for (int nt = 0; nt < 8; ++nt) {
                const int nb = brow0 + nt * (8 * STRIDE) + k0;
                bf[nt][0] = __float_as_uint(Bs[nb]);
                bf[nt][1] = __float_as_uint(Bs[nb + 4]);
            }
#pragma unroll
            for (int mt = 0; mt < 4; ++mt)
#pragma unroll
                for (int nt = 0; nt < 8; ++nt)
                    MMA_TF32(acc[mt][nt], af[mt], bf[nt]);
        }
    }

    // ---------------- epilogue ----------------
    if (MODE == 0 || MODE == 2 || MODE == 3) {
        float* Cb = C + (long long)z * sC;
#pragma unroll
        for (int mt = 0; mt < 4; ++mt) {
#pragma unroll
            for (int nt = 0; nt < 8; ++nt) {
                const int mA = m0 + wm * 64 + mt * 16 + g;
                const int n  = n0 + wn * 64 + nt * 8 + tg * 2;
                float v0 = acc[mt][nt][0], v1 = acc[mt][nt][1];
                float v2 = acc[mt][nt][2], v3 = acc[mt][nt][3];
                if (MODE == 0) {
                    const float b0 = bias[n], b1 = bias[n + 1];
                    v0 = to_tf32(v0 + b0); v1 = to_tf32(v1 + b1);
                    v2 = to_tf32(v2 + b0); v3 = to_tf32(v3 + b1);
                }
                if (MODE == 2) {
                    const float mb0 = (1.0f - mask[(long long)z * N + n]) * NEGF;
                    const float mb1 = (1.0f - mask[(long long)z * N + n + 1]) * NEGF;
                    v0 = v0 * scale + mb0; v1 = v1 * scale + mb1;
                    v2 = v2 * scale + mb0; v3 = v3 * scale + mb1;
                }
                *(float2*)(Cb + (long long)mA * N + n)       = make_float2(v0, v1);
                *(float2*)(Cb + (long long)(mA + 8) * N + n) = make_float2(v2, v3);
            }
        }
    } else {
        // transposed store via smem staging, four 64-col chunks (chunk = wn)
        float* Csh = sh;  // [128][65]
#pragma unroll 1
        for (int ch = 0; ch < 4; ++ch) {
            __syncthreads();
            if (wn == ch) {
#pragma unroll
                for (int mt = 0; mt < 4; ++mt) {
#pragma unroll
                    for (int nt = 0; nt < 8; ++nt) {
                        const int ml = wm * 64 + mt * 16 + g;
                        const int nl = nt * 8 + tg * 2;
                        float v0 = acc[mt][nt][0], v1 = acc[mt][nt][1];
                        float v2 = acc[mt][nt][2], v3 = acc[mt][nt][3];
                        if (MODE == 1) {
                            const float b0 = bias[n0 + ch * 64 + nl];
                            const float b1 = bias[n0 + ch * 64 + nl + 1];
                            v0 = to_tf32(v0 + b0); v1 = to_tf32(v1 + b1);
                            v2 = to_tf32(v2 + b0); v3 = to_tf32(v3 + b1);
                        }
                        if (MODE == 4) {
                            const float mk0 = mask[(long long)z * M + m0 + ml];
                            const float mk1 = mask[(long long)z * M + m0 + ml + 8];
                            v0 = to_tf32(v0 * mk0); v1 = to_tf32(v1 * mk0);
                            v2 = to_tf32(v2 * mk1); v3 = to_tf32(v3 * mk1);
                        }
                        Csh[ml * 65 + nl]           = v0;
                        Csh[ml * 65 + nl + 1]       = v1;
                        Csh[(ml + 8) * 65 + nl]     = v2;
                        Csh[(ml + 8) * 65 + nl + 1] = v3;
                    }
                }
            }
            __syncthreads();
#pragma unroll
            for (int i = 0; i < 32; ++i) {
                const int idx = tid + i * 256;
                const int nl = idx >> 7, m = idx & 127;
                C[(long long)z * sC + (long long)(n0 + ch * 64 + nl) * M + m0 + m] =
                    Csh[m * 65 + nl];
            }
        }
    }
}

// ---------------- tf32 pre-round of external GEMM inputs ----------------
__global__ __launch_bounds__(256)
void round_k(const float4* __restrict__ in, float4* __restrict__ out, int n4)
{
    const int i = blockIdx.x * 256 + threadIdx.x;
    if (i < n4) {
        float4 v = in[i];
        out[i] = make_float4(to_tf32(v.x), to_tf32(v.y), to_tf32(v.z), to_tf32(v.w));
    }
}

// ---------------- softmax helpers ----------------
__global__ __launch_bounds__(256)
void colstats_k(const float* __restrict__ S, float* __restrict__ cmax, float* __restrict__ crcp)
{
    const int z = blockIdx.y;
    const int m = blockIdx.x * 256 + threadIdx.x;
    const float* p = S + (long long)z * LSEQ * LSEQ + m;
    float mx = -3.4e38f;
#pragma unroll 4
    for (int l = 0; l < LSEQ; ++l) mx = fmaxf(mx, p[(long long)l * LSEQ]);
    float sm = 0.0f;
#pragma unroll 4
    for (int l = 0; l < LSEQ; ++l) sm += expf(p[(long long)l * LSEQ] - mx);
    cmax[z * LSEQ + m] = mx;
    crcp[z * LSEQ + m] = 1.0f / sm;
}

__global__ __launch_bounds__(256)
void a1t_k(const float* __restrict__ S, float* __restrict__ A1T,
           const float* __restrict__ cmax, const float* __restrict__ crcp)
{
    __shared__ float t[32][33];
    const int z = blockIdx.z;
    const int x0 = blockIdx.x * 32;  // m (L2)
    const int y0 = blockIdx.y * 32;  // l (L1)
    const int tx = threadIdx.x, ty = threadIdx.y;
    const float* Sb = S + (long long)z * LSEQ * LSEQ;
#pragma unroll
    for (int r = 0; r < 4; ++r)
        t[ty + r * 8][tx] = Sb[(long long)(y0 + ty + r * 8) * LSEQ + x0 + tx];
    __syncthreads();
#pragma unroll
    for (int r = 0; r < 4; ++r) {
        const int m = x0 + ty + r * 8;
        const int l = y0 + tx;
        const float v = t[tx][ty + r * 8];
        A1T[(long long)z * LSEQ * LSEQ + (long long)m * LSEQ + l] =
            to_tf32(expf(v - cmax[z * LSEQ + m]) * crcp[z * LSEQ + m]);
    }
}

__global__ __launch_bounds__(256)
void row_softmax_k(float* __restrict__ S)
{
    __shared__ float sred[8];
    const long long row = blockIdx.x;
    float* p = S + row * LSEQ;
    const int tid = threadIdx.x;
    float v[8];
#pragma unroll
    for (int i = 0; i < 8; ++i) v[i] = p[tid + i * 256];

    float mx = v[0];
#pragma unroll
    for (int i = 1; i < 8; ++i) mx = fmaxf(mx, v[i]);
#pragma unroll
    for (int o = 16; o; o >>= 1) mx = fmaxf(mx, __shfl_xor_sync(0xffffffffu, mx, o));
    if ((tid & 31) == 0) sred[tid >> 5] = mx;
    __syncthreads();
    float m2 = sred[0];
#pragma unroll
    for (int j = 1; j < 8; ++j) m2 = fmaxf(m2, sred[j]);
    __syncthreads();

    float sm = 0.0f;
#pragma unroll
    for (int i = 0; i < 8; ++i) { v[i] = expf(v[i] - m2); sm += v[i]; }
#pragma unroll
    for (int o = 16; o; o >>= 1) sm += __shfl_xor_sync(0xffffffffu, sm, o);
    if ((tid & 31) == 0) sred[tid >> 5] = sm;
    __syncthreads();
    float s2 = 0.0f;
#pragma unroll
    for (int j = 0; j < 8; ++j) s2 += sred[j];
    const float r = 1.0f / s2;
#pragma unroll
    for (int i = 0; i < 8; ++i) p[tid + i * 256] = to_tf32(v[i] * r);
}

// ---------------- launcher ----------------
extern "C" void kernel_launch(void* const* d_in, const int* in_sizes, int n_in,
                              void* d_out, int out_size)
{
    const float* x1   = (const float*)d_in[0];
    const float* x2   = (const float*)d_in[1];
    const float* mask = (const float*)d_in[2];
    const float* Wq   = (const float*)d_in[3];
    const float* bq   = (const float*)d_in[4];
    const float* Wk   = (const float*)d_in[5];
    const float* bk   = (const float*)d_in[6];
    const float* Wv   = (const float*)d_in[7];
    const float* bv   = (const float*)d_in[8];

    float* out1 = (float*)d_out;
    float* out2 = out1 + (long long)BATCH * LSEQ * DDIM;

    float *Q, *Kb, *V1T, *V2T, *XmT, *S, *A1T, *cmax, *crcp;
    float *x1r, *x2r, *Wqr, *Wkr, *Wvr;
    cudaGetSymbolAddress((void**)&Q,    g_Q);
    cudaGetSymbolAddress((void**)&Kb,   g_K);
    cudaGetSymbolAddress((void**)&V1T,  g_V1T);
    cudaGetSymbolAddress((void**)&V2T,  g_V2T);
    cudaGetSymbolAddress((void**)&XmT,  g_XmT);
    cudaGetSymbolAddress((void**)&S,    g_S);
    cudaGetSymbolAddress((void**)&A1T,  g_A1T);
    cudaGetSymbolAddress((void**)&cmax, g_cmax);
    cudaGetSymbolAddress((void**)&crcp, g_crcp);
    cudaGetSymbolAddress((void**)&x1r,  g_x1r);
    cudaGetSymbolAddress((void**)&x2r,  g_x2r);
    cudaGetSymbolAddress((void**)&Wqr,  g_Wqr);
    cudaGetSymbolAddress((void**)&Wkr,  g_Wkr);
    cudaGetSymbolAddress((void**)&Wvr,  g_Wvr);

    cudaFuncSetAttribute(gemm_tc<0>, cudaFuncAttributeMaxDynamicSharedMemorySize, SMEM_TOTAL);
    cudaFuncSetAttribute(gemm_tc<1>, cudaFuncAttributeMaxDynamicSharedMemorySize, SMEM_TOTAL);
    cudaFuncSetAttribute(gemm_tc<2>, cudaFuncAttributeMaxDynamicSharedMemorySize, SMEM_TOTAL);
    cudaFuncSetAttribute(gemm_tc<3>, cudaFuncAttributeMaxDynamicSharedMemorySize, SMEM_TOTAL);
    cudaFuncSetAttribute(gemm_tc<4>, cudaFuncAttributeMaxDynamicSharedMemorySize, SMEM_TOTAL);

    const long long sX = (long long)LSEQ * DDIM;
    const long long sT = (long long)DDIM * LSEQ;
    const long long sS = (long long)LSEQ * LSEQ;
    const float scale = 0.03125f;  // 1/sqrt(1024)

    // pre-round external inputs to tf32 values (GEMM inputs become tf32-exact)
    {
        const int nX4 = (int)((long long)BATCH * LSEQ * DDIM / 4);
        const int nW4 = DDIM * DDIM / 4;
        round_k<<<(nX4 + 255) / 256, 256>>>((const float4*)x1, (float4*)x1r, nX4);
        round_k<<<(nX4 + 255) / 256, 256>>>((const float4*)x2, (float4*)x2r, nX4);
        round_k<<<(nW4 + 255) / 256, 256>>>((const float4*)Wq, (float4*)Wqr, nW4);
        round_k<<<(nW4 + 255) / 256, 256>>>((const float4*)Wk, (float4*)Wkr, nW4);
        round_k<<<(nW4 + 255) / 256, 256>>>((const float4*)Wv, (float4*)Wvr, nW4);
    }

    dim3 blk(NTHREADS);
    dim3 gProj(DDIM / 256, LSEQ / 128, BATCH);   // (4,16,8)
    dim3 gS(LSEQ / 256, LSEQ / 128, BATCH);      // (8,16,8)

    // projections (outputs rounded to tf32 in epilogue)
    gemm_tc<0><<<gProj, blk, SMEM_TOTAL>>>(x1r, Wqr, Q,   LSEQ, DDIM, DDIM, sX, 0, sX, bq, nullptr, 0.f);
    gemm_tc<0><<<gProj, blk, SMEM_TOTAL>>>(x2r, Wkr, Kb,  LSEQ, DDIM, DDIM, sX, 0, sX, bk, nullptr, 0.f);
    gemm_tc<1><<<gProj, blk, SMEM_TOTAL>>>(x1r, Wvr, V1T, LSEQ, DDIM, DDIM, sX, 0, sT, bv, nullptr, 0.f);
    gemm_tc<1><<<gProj, blk, SMEM_TOTAL>>>(x2r, Wvr, V2T, LSEQ, DDIM, DDIM, sX, 0, sT, bv, nullptr, 0.f);

    // logits with scale + additive mask (fp32 out, feeds softmax)
    gemm_tc<2><<<gS, blk, SMEM_TOTAL>>>(Q, Kb, S, LSEQ, LSEQ, DDIM, sX, sX, sS, nullptr, mask, scale);

    // softmaxes (outputs rounded to tf32)
    colstats_k<<<dim3(LSEQ / 256, BATCH), blk>>>(S, cmax, crcp);
    a1t_k<<<dim3(LSEQ / 32, LSEQ / 32, BATCH), dim3(32, 8)>>>(S, A1T, cmax, crcp);
    row_softmax_k<<<BATCH * LSEQ, blk>>>(S);   // S becomes A2 in place

    // x2_out = A2 @ V2
    gemm_tc<3><<<gProj, blk, SMEM_TOTAL>>>(S, V2T, out2, LSEQ, DDIM, LSEQ, sS, sT, sX, nullptr, nullptr, 0.f);
    // x1_mid^T = (A1^T @ V1) * mask, stored [D, L2], rounded
    gemm_tc<4><<<gProj, blk, SMEM_TOTAL>>>(A1T, V1T, XmT, LSEQ, DDIM, LSEQ, sS, sT, sT, nullptr, mask, 0.f);
    // x1_out = A2 @ x1_mid
    gemm_tc<3><<<gProj, blk, SMEM_TOTAL>>>(S, XmT, out1, LSEQ, DDIM, LSEQ, sS, sT, sX, nullptr, nullptr, 0.f);
}

// round 7
// speedup vs baseline: 2.0302x; 1.6291x over previous
#include <cuda_runtime.h>
#include <cuda_fp16.h>
#include <math.h>
#include <stdint.h>

// Problem constants
#define BATCH 8
#define LSEQ  2048
#define DDIM  1024
#define NEGF  (-1e30f)

// GEMM tiling: CTA 128(M) x 256(N) x 64(K halves), 8 warps as 2(m) x 4(n), warp tile 64x64
#define NTHREADS 256
#define STAGES 3
#define STRIDE_W 36                         // words per smem row (64 halves data + 8 pad)
#define A_WORDS (128 * STRIDE_W)            // 4608
#define B_WORDS (256 * STRIDE_W)            // 9216
#define STAGE_WORDS (A_WORDS + B_WORDS)     // 13824
#define STAGE_BYTES (STAGE_WORDS * 4)       // 55296
#define A_BYTES (A_WORDS * 4)               // 18432
#define SMEM_TOTAL (STAGES * STAGE_BYTES)   // 165888

// ---------------- scratch (device globals; no allocation allowed) ----------------
__device__ __half g_Qh [(size_t)BATCH * LSEQ * DDIM];
__device__ __half g_Kh [(size_t)BATCH * LSEQ * DDIM];
__device__ __half g_V1T[(size_t)BATCH * DDIM * LSEQ];
__device__ __half g_V2T[(size_t)BATCH * DDIM * LSEQ];
__device__ __half g_XmT[(size_t)BATCH * DDIM * LSEQ];
__device__ float  g_S  [(size_t)BATCH * LSEQ * LSEQ];   // fp32 logits
__device__ __half g_A1T[(size_t)BATCH * LSEQ * LSEQ];
__device__ __half g_A2h[(size_t)BATCH * LSEQ * LSEQ];
__device__ float  g_cmax[BATCH * LSEQ];
__device__ float  g_crcp[BATCH * LSEQ];
__device__ __half g_x1h[(size_t)BATCH * LSEQ * DDIM];
__device__ __half g_x2h[(size_t)BATCH * LSEQ * DDIM];
__device__ __half g_Wqh[(size_t)DDIM * DDIM];
__device__ __half g_Wkh[(size_t)DDIM * DDIM];
__device__ __half g_Wvh[(size_t)DDIM * DDIM];

// ---------------- helpers ----------------
__device__ __forceinline__ uint32_t smem_to_u32(const void* p) {
    uint32_t a;
    asm("{ .reg .u64 t; cvta.to.shared.u64 t, %1; cvt.u32.u64 %0, t; }" : "=r"(a) : "l"(p));
    return a;
}

#define CP_ASYNC16(dst, src) \
    asm volatile("cp.async.cg.shared.global [%0], [%1], 16;" :: "r"(dst), "l"(src) : "memory")
#define CP_COMMIT() asm volatile("cp.async.commit_group;" ::: "memory")

// m16n8k16 fp16 MMA, fp32 accumulate
#define MMA_F16(d, a, b)                                                   \
    asm volatile(                                                          \
        "mma.sync.aligned.m16n8k16.row.col.f32.f16.f16.f32 "               \
        "{%0,%1,%2,%3}, {%4,%5,%6,%7}, {%8,%9}, {%0,%1,%2,%3};"            \
        : "+f"(d[0]), "+f"(d[1]), "+f"(d[2]), "+f"(d[3])                   \
        : "r"(a[0]), "r"(a[1]), "r"(a[2]), "r"(a[3]), "r"(b[0]), "r"(b[1]))

// ---------------------------------------------------------------------------
// Batched NT GEMM: C[m,n] = sum_k A[m,k]*B[n,k]; A,B are __half [rows, K].
// MODE 0: +bias[n], HALF out, normal store
// MODE 1: +bias[n], HALF out, transposed store C[n,m]
// MODE 2: *scale + (1-mask[z,n])*NEG, FLOAT out, normal store
// MODE 3: plain FLOAT out, normal store
// MODE 4: *mask[z,m], HALF out, transposed store C[n,m]
// Requires M%128==0, N%256==0, K%64==0. Strides in elements.
// ---------------------------------------------------------------------------
template <int MODE>
__global__ __launch_bounds__(NTHREADS, 1)
void gemm_hc(const __half* __restrict__ A, const __half* __restrict__ B, void* __restrict__ Cv,
             int M, int N, int K, long long sA, long long sB, long long sC,
             const float* __restrict__ bias, const float* __restrict__ mask, float scale)
{
    extern __shared__ char smc[];
    const uint32_t smem_u = smem_to_u32(smc);
    const int tid = threadIdx.x, wid = tid >> 5, lane = tid & 31;
    const int wm = wid & 1, wn = wid >> 1;      // 2 x 4 warps
    const int g = lane >> 2, tg = lane & 3;
    const int z = blockIdx.z;
    const int m0 = blockIdx.y * 128;
    const int n0 = blockIdx.x * 256;

    const __half* Abase = A + (long long)z * sA + (long long)m0 * K;
    const __half* Bbase = B + (long long)z * sB + (long long)n0 * K;
    const int T = K >> 6;                       // 64 halves per k-tile

    // cp.async staging: rows of 64 halves = 128B = 8 chunks of 16B
    const int sr = tid >> 3;                    // 0..31 (row within group of 32)
    const int sj = tid & 7;                     // chunk 0..7
    auto stage = [&](int u) {
        const int s = u % STAGES;
        const uint32_t sa = smem_u + s * STAGE_BYTES;
        const uint32_t sb = sa + A_BYTES;
        const __half* Asrc = Abase + (size_t)u * 64;
        const __half* Bsrc = Bbase + (size_t)u * 64;
        const uint32_t dw = sj * 16;            // byte offset within row (4 words/chunk)
#pragma unroll
        for (int i = 0; i < 4; ++i) {
            const int r = sr + i * 32;
            CP_ASYNC16(sa + r * (STRIDE_W * 4) + dw, Asrc + (size_t)r * K + sj * 8);
        }
#pragma unroll
        for (int i = 0; i < 8; ++i) {
            const int r = sr + i * 32;
            CP_ASYNC16(sb + r * (STRIDE_W * 4) + dw, Bsrc + (size_t)r * K + sj * 8);
        }
        CP_COMMIT();
    };

    float acc[4][8][4];
#pragma unroll
    for (int a = 0; a < 4; ++a)
#pragma unroll
        for (int b = 0; b < 8; ++b)
#pragma unroll
            for (int c = 0; c < 4; ++c) acc[a][b][c] = 0.0f;

    stage(0);
    stage(1);

    const int arow0 = (wm * 64 + g) * STRIDE_W;
    const int brow0 = (wn * 64 + g) * STRIDE_W;

    for (int t = 0; t < T; ++t) {
        if (t < T - 1) asm volatile("cp.async.wait_group 1;" ::: "memory");
        else           asm volatile("cp.async.wait_group 0;" ::: "memory");
        __syncthreads();

        if (t + 2 < T) stage(t + 2);

        const uint32_t* As32 = (const uint32_t*)(smc + (t % STAGES) * STAGE_BYTES);
        const uint32_t* Bs32 = (const uint32_t*)(smc + (t % STAGES) * STAGE_BYTES + A_BYTES);
#pragma unroll
        for (int ks = 0; ks < 4; ++ks) {        // 4 k16 steps per 64-half tile
            const int k0 = ks * 8 + tg;         // word offset within row
            uint32_t af[4][4], bf[8][2];
#pragma unroll
            for (int mt = 0; mt < 4; ++mt) {
                const int rb = arow0 + mt * (16 * STRIDE_W) + k0;
                af[mt][0] = As32[rb];
                af[mt][1] = As32[rb + 8 * STRIDE_W];
                af[mt][2] = As32[rb + 4];
                af[mt][3] = As32[rb + 8 * STRIDE_W + 4];
            }
#pragma unroll
            for (int nt = 0; nt < 8; ++nt) {
                const int nb = brow0 + nt * (8 * STRIDE_W) + k0;
                bf[nt][0] = Bs32[nb];
                bf[nt][1] = Bs32[nb + 4];
            }
#pragma unroll
            for (int mt = 0; mt < 4; ++mt)
#pragma unroll
                for (int nt = 0; nt < 8; ++nt)
                    MMA_F16(acc[mt][nt], af[mt], bf[nt]);
        }
    }

    // ---------------- epilogue ----------------
    if (MODE == 0) {
        __half* Cb = (__half*)Cv + (long long)z * sC;
#pragma unroll
        for (int mt = 0; mt < 4; ++mt)
#pragma unroll
            for (int nt = 0; nt < 8; ++nt) {
                const int mA = m0 + wm * 64 + mt * 16 + g;
                const int n  = n0 + wn * 64 + nt * 8 + tg * 2;
                const float b0 = bias[n], b1 = bias[n + 1];
                *(__half2*)(Cb + (long long)mA * N + n) =
                    __floats2half2_rn(acc[mt][nt][0] + b0, acc[mt][nt][1] + b1);
                *(__half2*)(Cb + (long long)(mA + 8) * N + n) =
                    __floats2half2_rn(acc[mt][nt][2] + b0, acc[mt][nt][3] + b1);
            }
    } else if (MODE == 2 || MODE == 3) {
        float* Cb = (float*)Cv + (long long)z * sC;
#pragma unroll
        for (int mt = 0; mt < 4; ++mt)
#pragma unroll
            for (int nt = 0; nt < 8; ++nt) {
                const int mA = m0 + wm * 64 + mt * 16 + g;
                const int n  = n0 + wn * 64 + nt * 8 + tg * 2;
                float v0 = acc[mt][nt][0], v1 = acc[mt][nt][1];
                float v2 = acc[mt][nt][2], v3 = acc[mt][nt][3];
                if (MODE == 2) {
                    const float mb0 = (1.0f - mask[(long long)z * N + n]) * NEGF;
                    const float mb1 = (1.0f - mask[(long long)z * N + n + 1]) * NEGF;
                    v0 = v0 * scale + mb0; v1 = v1 * scale + mb1;
                    v2 = v2 * scale + mb0; v3 = v3 * scale + mb1;
                }
                *(float2*)(Cb + (long long)mA * N + n)       = make_float2(v0, v1);
                *(float2*)(Cb + (long long)(mA + 8) * N + n) = make_float2(v2, v3);
            }
    } else {
        // transposed HALF store via smem staging, four 64-col chunks (chunk = wn)
        float* Csh = (float*)smc;   // [128][65]
        __half* Cb = (__half*)Cv + (long long)z * sC;
#pragma unroll 1
        for (int ch = 0; ch < 4; ++ch) {
            __syncthreads();
            if (wn == ch) {
#pragma unroll
                for (int mt = 0; mt < 4; ++mt)
#pragma unroll
                    for (int nt = 0; nt < 8; ++nt) {
                        const int ml = wm * 64 + mt * 16 + g;
                        const int nl = nt * 8 + tg * 2;
                        float v0 = acc[mt][nt][0], v1 = acc[mt][nt][1];
                        float v2 = acc[mt][nt][2], v3 = acc[mt][nt][3];
                        if (MODE == 1) {
                            const float b0 = bias[n0 + ch * 64 + nl];
                            const float b1 = bias[n0 + ch * 64 + nl + 1];
                            v0 += b0; v1 += b1; v2 += b0; v3 += b1;
                        }
                        if (MODE == 4) {
                            const float mk0 = mask[(long long)z * M + m0 + ml];
                            const float mk1 = mask[(long long)z * M + m0 + ml + 8];
                            v0 *= mk0; v1 *= mk0; v2 *= mk1; v3 *= mk1;
                        }
                        Csh[ml * 65 + nl]           = v0;
                        Csh[ml * 65 + nl + 1]       = v1;
                        Csh[(ml + 8) * 65 + nl]     = v2;
                        Csh[(ml + 8) * 65 + nl + 1] = v3;
                    }
            }
            __syncthreads();
#pragma unroll
            for (int i = 0; i < 32; ++i) {
                const int idx = tid + i * 256;
                const int nl = idx >> 7, m = idx & 127;
                Cb[(long long)(n0 + ch * 64 + nl) * M + m0 + m] =
                    __float2half_rn(Csh[m * 65 + nl]);
            }
        }
    }
}

// ---------------- fp32 -> fp16 conversion of external GEMM inputs ----------------
__global__ __launch_bounds__(256)
void cvt_h(const float4* __restrict__ in, __half2* __restrict__ out, int n4)
{
    const int i = blockIdx.x * 256 + threadIdx.x;
    if (i < n4) {
        float4 v = in[i];
        out[2 * i]     = __floats2half2_rn(v.x, v.y);
        out[2 * i + 1] = __floats2half2_rn(v.z, v.w);
    }
}

// ---------------- softmax helpers ----------------
__global__ __launch_bounds__(256)
void colstats_k(const float* __restrict__ S, float* __restrict__ cmax, float* __restrict__ crcp)
{
    const int z = blockIdx.y;
    const int m = blockIdx.x * 256 + threadIdx.x;
    const float* p = S + (long long)z * LSEQ * LSEQ + m;
    float mx = -3.4e38f;
#pragma unroll 4
    for (int l = 0; l < LSEQ; ++l) mx = fmaxf(mx, p[(long long)l * LSEQ]);
    float sm = 0.0f;
#pragma unroll 4
    for (int l = 0; l < LSEQ; ++l) sm += expf(p[(long long)l * LSEQ] - mx);
    cmax[z * LSEQ + m] = mx;
    crcp[z * LSEQ + m] = 1.0f / sm;
}

// A1T[b, m, l] = exp(S[b,l,m] - cmax[b,m]) * crcp[b,m]   (half out, 32x32 transpose)
__global__ __launch_bounds__(256)
void a1t_k(const float* __restrict__ S, __half* __restrict__ A1T,
           const float* __restrict__ cmax, const float* __restrict__ crcp)
{
    __shared__ float t[32][33];
    const int z = blockIdx.z;
    const int x0 = blockIdx.x * 32;  // m (L2)
    const int y0 = blockIdx.y * 32;  // l (L1)
    const int tx = threadIdx.x, ty = threadIdx.y;
    const float* Sb = S + (long long)z * LSEQ * LSEQ;
#pragma unroll
    for (int r = 0; r < 4; ++r)
        t[ty + r * 8][tx] = Sb[(long long)(y0 + ty + r * 8) * LSEQ + x0 + tx];
    __syncthreads();
#pragma unroll
    for (int r = 0; r < 4; ++r) {
        const int m = x0 + ty + r * 8;
        const int l = y0 + tx;
        const float v = t[tx][ty + r * 8];
        A1T[(long long)z * LSEQ * LSEQ + (long long)m * LSEQ + l] =
            __float2half_rn(expf(v - cmax[z * LSEQ + m]) * crcp[z * LSEQ + m]);
    }
}

// row softmax over L2: reads fp32 S, writes half A2
__global__ __launch_bounds__(256)
void row_softmax_k(const float* __restrict__ S, __half* __restrict__ A2)
{
    __shared__ float sred[8];
    const long long row = blockIdx.x;
    const float* p = S + row * LSEQ;
    __half* po = A2 + row * LSEQ;
    const int tid = threadIdx.x;
    float v[8];
#pragma unroll
    for (int i = 0; i < 8; ++i) v[i] = p[tid + i * 256];

    float mx = v[0];
#pragma unroll
    for (int i = 1; i < 8; ++i) mx = fmaxf(mx, v[i]);
#pragma unroll
    for (int o = 16; o; o >>= 1) mx = fmaxf(mx, __shfl_xor_sync(0xffffffffu, mx, o));
    if ((tid & 31) == 0) sred[tid >> 5] = mx;
    __syncthreads();
    float m2 = sred[0];
#pragma unroll
    for (int j = 1; j < 8; ++j) m2 = fmaxf(m2, sred[j]);
    __syncthreads();

    float sm = 0.0f;
#pragma unroll
    for (int i = 0; i < 8; ++i) { v[i] = expf(v[i] - m2); sm += v[i]; }
#pragma unroll
    for (int o = 16; o; o >>= 1) sm += __shfl_xor_sync(0xffffffffu, sm, o);
    if ((tid & 31) == 0) sred[tid >> 5] = sm;
    __syncthreads();
    float s2 = 0.0f;
#pragma unroll
    for (int j = 0; j < 8; ++j) s2 += sred[j];
    const float r = 1.0f / s2;
#pragma unroll
    for (int i = 0; i < 8; ++i) po[tid + i * 256] = __float2half_rn(v[i] * r);
}

// ---------------- launcher ----------------
extern "C" void kernel_launch(void* const* d_in, const int* in_sizes, int n_in,
                              void* d_out, int out_size)
{
    const float* x1   = (const float*)d_in[0];
    const float* x2   = (const float*)d_in[1];
    const float* mask = (const float*)d_in[2];
    const float* Wq   = (const float*)d_in[3];
    const float* bq   = (const float*)d_in[4];
    const float* Wk   = (const float*)d_in[5];
    const float* bk   = (const float*)d_in[6];
    const float* Wv   = (const float*)d_in[7];
    const float* bv   = (const float*)d_in[8];

    float* out1 = (float*)d_out;
    float* out2 = out1 + (long long)BATCH * LSEQ * DDIM;

    __half *Qh, *Kh, *V1T, *V2T, *XmT, *A1T, *A2h, *x1h, *x2h, *Wqh, *Wkh, *Wvh;
    float *S, *cmax, *crcp;
    cudaGetSymbolAddress((void**)&Qh,   g_Qh);
    cudaGetSymbolAddress((void**)&Kh,   g_Kh);
    cudaGetSymbolAddress((void**)&V1T,  g_V1T);
    cudaGetSymbolAddress((void**)&V2T,  g_V2T);
    cudaGetSymbolAddress((void**)&XmT,  g_XmT);
    cudaGetSymbolAddress((void**)&S,    g_S);
    cudaGetSymbolAddress((void**)&A1T,  g_A1T);
    cudaGetSymbolAddress((void**)&A2h,  g_A2h);
    cudaGetSymbolAddress((void**)&cmax, g_cmax);
    cudaGetSymbolAddress((void**)&crcp, g_crcp);
    cudaGetSymbolAddress((void**)&x1h,  g_x1h);
    cudaGetSymbolAddress((void**)&x2h,  g_x2h);
    cudaGetSymbolAddress((void**)&Wqh,  g_Wqh);
    cudaGetSymbolAddress((void**)&Wkh,  g_Wkh);
    cudaGetSymbolAddress((void**)&Wvh,  g_Wvh);

    cudaFuncSetAttribute(gemm_hc<0>, cudaFuncAttributeMaxDynamicSharedMemorySize, SMEM_TOTAL);
    cudaFuncSetAttribute(gemm_hc<1>, cudaFuncAttributeMaxDynamicSharedMemorySize, SMEM_TOTAL);
    cudaFuncSetAttribute(gemm_hc<2>, cudaFuncAttributeMaxDynamicSharedMemorySize, SMEM_TOTAL);
    cudaFuncSetAttribute(gemm_hc<3>, cudaFuncAttributeMaxDynamicSharedMemorySize, SMEM_TOTAL);
    cudaFuncSetAttribute(gemm_hc<4>, cudaFuncAttributeMaxDynamicSharedMemorySize, SMEM_TOTAL);

    const long long sX = (long long)LSEQ * DDIM;
    const long long sT = (long long)DDIM * LSEQ;
    const long long sS = (long long)LSEQ * LSEQ;
    const float scale = 0.03125f;  // 1/sqrt(1024)

    // convert external inputs to fp16
    {
        const int nX4 = (int)((long long)BATCH * LSEQ * DDIM / 4);
        const int nW4 = DDIM * DDIM / 4;
        cvt_h<<<(nX4 + 255) / 256, 256>>>((const float4*)x1, (__half2*)x1h, nX4);
        cvt_h<<<(nX4 + 255) / 256, 256>>>((const float4*)x2, (__half2*)x2h, nX4);
        cvt_h<<<(nW4 + 255) / 256, 256>>>((const float4*)Wq, (__half2*)Wqh, nW4);
        cvt_h<<<(nW4 + 255) / 256, 256>>>((const float4*)Wk, (__half2*)Wkh, nW4);
        cvt_h<<<(nW4 + 255) / 256, 256>>>((const float4*)Wv, (__half2*)Wvh, nW4);
    }

    dim3 blk(NTHREADS);
    dim3 gProj(DDIM / 256, LSEQ / 128, BATCH);   // (4,16,8)
    dim3 gS(LSEQ / 256, LSEQ / 128, BATCH);      // (8,16,8)

    // projections (half outputs)
    gemm_hc<0><<<gProj, blk, SMEM_TOTAL>>>(x1h, Wqh, Qh,  LSEQ, DDIM, DDIM, sX, 0, sX, bq, nullptr, 0.f);
    gemm_hc<0><<<gProj, blk, SMEM_TOTAL>>>(x2h, Wkh, Kh,  LSEQ, DDIM, DDIM, sX, 0, sX, bk, nullptr, 0.f);
    gemm_hc<1><<<gProj, blk, SMEM_TOTAL>>>(x1h, Wvh, V1T, LSEQ, DDIM, DDIM, sX, 0, sT, bv, nullptr, 0.f);
    gemm_hc<1><<<gProj, blk, SMEM_TOTAL>>>(x2h, Wvh, V2T, LSEQ, DDIM, DDIM, sX, 0, sT, bv, nullptr, 0.f);

    // logits with scale + additive mask (fp32 out, feeds softmax)
    gemm_hc<2><<<gS, blk, SMEM_TOTAL>>>(Qh, Kh, S, LSEQ, LSEQ, DDIM, sX, sX, sS, nullptr, mask, scale);

    // softmaxes (half outputs)
    colstats_k<<<dim3(LSEQ / 256, BATCH), blk>>>(S, cmax, crcp);
    a1t_k<<<dim3(LSEQ / 32, LSEQ / 32, BATCH), dim3(32, 8)>>>(S, A1T, cmax, crcp);
    row_softmax_k<<<BATCH * LSEQ, blk>>>(S, A2h);

    // x2_out = A2 @ V2
    gemm_hc<3><<<gProj, blk, SMEM_TOTAL>>>(A2h, V2T, out2, LSEQ, DDIM, LSEQ, sS, sT, sX, nullptr, nullptr, 0.f);
    // x1_mid^T = (A1^T @ V1) * mask, stored [D, L2] half
    gemm_hc<4><<<gProj, blk, SMEM_TOTAL>>>(A1T, V1T, XmT, LSEQ, DDIM, LSEQ, sS, sT, sT, nullptr, mask, 0.f);
    // x1_out = A2 @ x1_mid
    gemm_hc<3><<<gProj, blk, SMEM_TOTAL>>>(A2h, XmT, out1, LSEQ, DDIM, LSEQ, sS, sT, sX, nullptr, nullptr, 0.f);
}

// round 8
// speedup vs baseline: 2.7485x; 1.3538x over previous
#include <cuda_runtime.h>
#include <cuda_fp16.h>
#include <math.h>
#include <stdint.h>

// Problem constants
#define BATCH 8
#define LSEQ  2048
#define DDIM  1024
#define NEGF  (-1e30f)

// GEMM tiling: CTA 128(M) x 256(N) x 64(K halves), 8 warps as 2(m) x 4(n), warp tile 64x64
#define NTHREADS 256
#define STAGES 3
#define ROW_BYTES 144                       // 64 halves (128B) + 16B pad
#define A_BYTES (128 * ROW_BYTES)           // 18432
#define B_BYTES (256 * ROW_BYTES)           // 36864
#define STAGE_BYTES (A_BYTES + B_BYTES)     // 55296
#define SMEM_TOTAL (STAGES * STAGE_BYTES)   // 165888

// ---------------- scratch (device globals; no allocation allowed) ----------------
__device__ __half g_Qh [(size_t)BATCH * LSEQ * DDIM];
__device__ __half g_Kh [(size_t)BATCH * LSEQ * DDIM];
__device__ __half g_V1T[(size_t)BATCH * DDIM * LSEQ];
__device__ __half g_V2T[(size_t)BATCH * DDIM * LSEQ];
__device__ __half g_XmT[(size_t)BATCH * DDIM * LSEQ];
__device__ float  g_S  [(size_t)BATCH * LSEQ * LSEQ];   // fp32 logits
__device__ __half g_A1T[(size_t)BATCH * LSEQ * LSEQ];
__device__ __half g_A2h[(size_t)BATCH * LSEQ * LSEQ];
__device__ float  g_rowsum[BATCH * LSEQ];
__device__ float  g_colsum[BATCH * LSEQ];
__device__ __half g_x1h[(size_t)BATCH * LSEQ * DDIM];
__device__ __half g_x2h[(size_t)BATCH * LSEQ * DDIM];
__device__ __half g_Wqh[(size_t)DDIM * DDIM];
__device__ __half g_Wkh[(size_t)DDIM * DDIM];
__device__ __half g_Wvh[(size_t)DDIM * DDIM];

// ---------------- helpers ----------------
__device__ __forceinline__ uint32_t smem_to_u32(const void* p) {
    uint32_t a;
    asm("{ .reg .u64 t; cvta.to.shared.u64 t, %1; cvt.u32.u64 %0, t; }" : "=r"(a) : "l"(p));
    return a;
}

#define CP_ASYNC16(dst, src) \
    asm volatile("cp.async.cg.shared.global [%0], [%1], 16;" :: "r"(dst), "l"(src) : "memory")
#define CP_COMMIT() asm volatile("cp.async.commit_group;" ::: "memory")

#define LDSM_X4(r, addr) \
    asm volatile("ldmatrix.sync.aligned.m8n8.x4.shared.b16 {%0,%1,%2,%3}, [%4];" \
        : "=r"((r)[0]), "=r"((r)[1]), "=r"((r)[2]), "=r"((r)[3]) : "r"(addr))

// m16n8k16 fp16 MMA, fp32 accumulate
#define MMA_F16(d, a, b)                                                   \
    asm volatile(                                                          \
        "mma.sync.aligned.m16n8k16.row.col.f32.f16.f16.f32 "               \
        "{%0,%1,%2,%3}, {%4,%5,%6,%7}, {%8,%9}, {%0,%1,%2,%3};"            \
        : "+f"(d[0]), "+f"(d[1]), "+f"(d[2]), "+f"(d[3])                   \
        : "r"(a[0]), "r"(a[1]), "r"(a[2]), "r"(a[3]), "r"(b[0]), "r"(b[1]))

// ---------------------------------------------------------------------------
// NT GEMM body: C[m,n] = sum_k A[m,k]*B[n,k]; A,B __half [rows, K] k-contig.
// MODE 0: +bias[n], HALF out, normal store
// MODE 1: +bias[n], HALF out, transposed store C[n,m]
// MODE 2: *scale + (1-mask[z,n])*NEG, FLOAT out, normal store
// MODE 3: plain FLOAT out, normal store
// MODE 4: *mask[z,m], HALF out, transposed store C[n,m]
// ---------------------------------------------------------------------------
template <int MODE>
__device__ __forceinline__
void gemm_body(const __half* __restrict__ A, const __half* __restrict__ B, void* __restrict__ Cv,
               int M, int N, int K, long long sA, long long sB, long long sC,
               const float* __restrict__ bias, const float* __restrict__ mask, float scale,
               int z, int m0, int n0, char* smc)
{
    const uint32_t smem_u = smem_to_u32(smc);
    const int tid = threadIdx.x, wid = tid >> 5, lane = tid & 31;
    const int wm = wid & 1, wn = wid >> 1;      // 2 x 4 warps
    const int g = lane >> 2, tg = lane & 3;

    const __half* Abase = A + (long long)z * sA + (long long)m0 * K;
    const __half* Bbase = B + (long long)z * sB + (long long)n0 * K;
    const int T = K >> 6;                       // 64 halves per k-tile

    // cp.async staging: rows of 64 halves = 128B = 8 chunks of 16B
    const int sr = tid >> 3;                    // 0..31
    const int sj = tid & 7;                     // chunk 0..7
    auto stage = [&](int u) {
        const int s = u % STAGES;
        const uint32_t sa = smem_u + s * STAGE_BYTES;
        const uint32_t sb = sa + A_BYTES;
        const __half* Asrc = Abase + (size_t)u * 64 + sj * 8;
        const __half* Bsrc = Bbase + (size_t)u * 64 + sj * 8;
        const uint32_t dw = sj * 16;
#pragma unroll
        for (int i = 0; i < 4; ++i) {
            const int r = sr + i * 32;
            CP_ASYNC16(sa + r * ROW_BYTES + dw, Asrc + (size_t)r * K);
        }
#pragma unroll
        for (int i = 0; i < 8; ++i) {
            const int r = sr + i * 32;
            CP_ASYNC16(sb + r * ROW_BYTES + dw, Bsrc + (size_t)r * K);
        }
        CP_COMMIT();
    };

    float acc[4][8][4];
#pragma unroll
    for (int a = 0; a < 4; ++a)
#pragma unroll
        for (int b = 0; b < 8; ++b)
#pragma unroll
            for (int c = 0; c < 4; ++c) acc[a][b][c] = 0.0f;

    stage(0);
    stage(1);

    // ldmatrix per-thread address offsets (bytes)
    // A: lanes 0-15 -> rows m0..15 (k byte 0); lanes 16-31 -> rows m0..15 (+16B)
    const uint32_t a_lm = (uint32_t)((wm * 64 + (lane & 15)) * ROW_BYTES + (lane >> 4) * 16);
    // B: lanes 0-7 n0-7 k0 | 8-15 n0-7 +16B | 16-23 n8-15 k0 | 24-31 n8-15 +16B
    const uint32_t b_lm = (uint32_t)((wn * 64 + ((lane >> 4) << 3) + (lane & 7)) * ROW_BYTES +
                                     ((lane >> 3) & 1) * 16);

    for (int t = 0; t < T; ++t) {
        if (t < T - 1) asm volatile("cp.async.wait_group 1;" ::: "memory");
        else           asm volatile("cp.async.wait_group 0;" ::: "memory");
        __syncthreads();

        if (t + 2 < T) stage(t + 2);

        const uint32_t sbase = smem_u + (t % STAGES) * STAGE_BYTES;
#pragma unroll
        for (int ks = 0; ks < 4; ++ks) {        // 4 k16 steps per 64-half tile
            const uint32_t abase = sbase + a_lm + ks * 32;
            const uint32_t bbase = sbase + A_BYTES + b_lm + ks * 32;
            uint32_t af[4][4], bf[4][4];
#pragma unroll
            for (int mt = 0; mt < 4; ++mt) LDSM_X4(af[mt], abase + mt * (16 * ROW_BYTES));
#pragma unroll
            for (int np = 0; np < 4; ++np) LDSM_X4(bf[np], bbase + np * (16 * ROW_BYTES));
#pragma unroll
            for (int mt = 0; mt < 4; ++mt)
#pragma unroll
                for (int nt = 0; nt < 8; ++nt)
                    MMA_F16(acc[mt][nt], af[mt], (bf[nt >> 1] + (nt & 1) * 2));
        }
    }

    // ---------------- epilogue ----------------
    if (MODE == 0) {
        __half* Cb = (__half*)Cv + (long long)z * sC;
#pragma unroll
        for (int mt = 0; mt < 4; ++mt)
#pragma unroll
            for (int nt = 0; nt < 8; ++nt) {
                const int mA = m0 + wm * 64 + mt * 16 + g;
                const int n  = n0 + wn * 64 + nt * 8 + tg * 2;
                const float b0 = bias[n], b1 = bias[n + 1];
                *(__half2*)(Cb + (long long)mA * N + n) =
                    __floats2half2_rn(acc[mt][nt][0] + b0, acc[mt][nt][1] + b1);
                *(__half2*)(Cb + (long long)(mA + 8) * N + n) =
                    __floats2half2_rn(acc[mt][nt][2] + b0, acc[mt][nt][3] + b1);
            }
    } else if (MODE == 2 || MODE == 3) {
        float* Cb = (float*)Cv + (long long)z * sC;
#pragma unroll
        for (int mt = 0; mt < 4; ++mt)
#pragma unroll
            for (int nt = 0; nt < 8; ++nt) {
                const int mA = m0 + wm * 64 + mt * 16 + g;
                const int n  = n0 + wn * 64 + nt * 8 + tg * 2;
                float v0 = acc[mt][nt][0], v1 = acc[mt][nt][1];
                float v2 = acc[mt][nt][2], v3 = acc[mt][nt][3];
                if (MODE == 2) {
                    const float mb0 = (1.0f - mask[(long long)z * N + n]) * NEGF;
                    const float mb1 = (1.0f - mask[(long long)z * N + n + 1]) * NEGF;
                    v0 = v0 * scale + mb0; v1 = v1 * scale + mb1;
                    v2 = v2 * scale + mb0; v3 = v3 * scale + mb1;
                }
                *(float2*)(Cb + (long long)mA * N + n)       = make_float2(v0, v1);
                *(float2*)(Cb + (long long)(mA + 8) * N + n) = make_float2(v2, v3);
            }
    } else {
        // transposed HALF store via smem staging, four 64-col chunks (chunk = wn)
        float* Csh = (float*)smc;   // [128][65]
        __half* Cb = (__half*)Cv + (long long)z * sC;
#pragma unroll 1
        for (int ch = 0; ch < 4; ++ch) {
            __syncthreads();
            if (wn == ch) {
#pragma unroll
                for (int mt = 0; mt < 4; ++mt)
#pragma unroll
                    for (int nt = 0; nt < 8; ++nt) {
                        const int ml = wm * 64 + mt * 16 + g;
                        const int nl = nt * 8 + tg * 2;
                        float v0 = acc[mt][nt][0], v1 = acc[mt][nt][1];
                        float v2 = acc[mt][nt][2], v3 = acc[mt][nt][3];
                        if (MODE == 1) {
                            const float b0 = bias[n0 + ch * 64 + nl];
                            const float b1 = bias[n0 + ch * 64 + nl + 1];
                            v0 += b0; v1 += b1; v2 += b0; v3 += b1;
                        }
                        if (MODE == 4) {
                            const float mk0 = mask[(long long)z * M + m0 + ml];
                            const float mk1 = mask[(long long)z * M + m0 + ml + 8];
                            v0 *= mk0; v1 *= mk0; v2 *= mk1; v3 *= mk1;
                        }
                        Csh[ml * 65 + nl]           = v0;
                        Csh[ml * 65 + nl + 1]       = v1;
                        Csh[(ml + 8) * 65 + nl]     = v2;
                        Csh[(ml + 8) * 65 + nl + 1] = v3;
                    }
            }
            __syncthreads();
#pragma unroll
            for (int i = 0; i < 32; ++i) {
                const int idx = tid + i * 256;
                const int nl = idx >> 7, m = idx & 127;
                Cb[(long long)(n0 + ch * 64 + nl) * M + m0 + m] =
                    __float2half_rn(Csh[m * 65 + nl]);
            }
        }
    }
}

// ---------------- GEMM kernel wrappers ----------------
__global__ __launch_bounds__(NTHREADS, 1)
void proj_dual_k(const __half* __restrict__ A,
                 const __half* __restrict__ B0, const __half* __restrict__ B1,
                 __half* __restrict__ C0, __half* __restrict__ C1,
                 const float* __restrict__ bias0, const float* __restrict__ bias1)
{
    extern __shared__ char smc[];
    const int z = blockIdx.z, m0 = blockIdx.y * 128, bx = blockIdx.x;
    const long long sX = (long long)LSEQ * DDIM;
    const long long sT = (long long)DDIM * LSEQ;
    if (bx < 4)
        gemm_body<0>(A, B0, C0, LSEQ, DDIM, DDIM, sX, 0, sX, bias0, nullptr, 0.f, z, m0, bx * 256, smc);
    else
        gemm_body<1>(A, B1, C1, LSEQ, DDIM, DDIM, sX, 0, sT, bias1, nullptr, 0.f, z, m0, (bx - 4) * 256, smc);
}

__global__ __launch_bounds__(NTHREADS, 1)
void sgemm_k(const __half* __restrict__ Q, const __half* __restrict__ Kh,
             float* __restrict__ S, const float* __restrict__ mask, float scale)
{
    extern __shared__ char smc[];
    const long long sX = (long long)LSEQ * DDIM;
    const long long sS = (long long)LSEQ * LSEQ;
    gemm_body<2>(Q, Kh, S, LSEQ, LSEQ, DDIM, sX, sX, sS, nullptr, mask, scale,
                 blockIdx.z, blockIdx.y * 128, blockIdx.x * 256, smc);
}

__global__ __launch_bounds__(NTHREADS, 1)
void apply_dual_k(const __half* __restrict__ A2, const __half* __restrict__ A1T,
                  const __half* __restrict__ V2T, const __half* __restrict__ V1T,
                  float* __restrict__ out2, __half* __restrict__ XmT,
                  const float* __restrict__ mask)
{
    extern __shared__ char smc[];
    const int m0 = blockIdx.y * 128, n0 = blockIdx.x * 256;
    const long long sX = (long long)LSEQ * DDIM;
    const long long sT = (long long)DDIM * LSEQ;
    const long long sS = (long long)LSEQ * LSEQ;
    if (blockIdx.z < 8)
        gemm_body<3>(A2, V2T, out2, LSEQ, DDIM, LSEQ, sS, sT, sX, nullptr, nullptr, 0.f,
                     blockIdx.z, m0, n0, smc);
    else
        gemm_body<4>(A1T, V1T, XmT, LSEQ, DDIM, LSEQ, sS, sT, sT, nullptr, mask, 0.f,
                     blockIdx.z - 8, m0, n0, smc);
}

__global__ __launch_bounds__(NTHREADS, 1)
void final_k(const __half* __restrict__ A2, const __half* __restrict__ XmT, float* __restrict__ out1)
{
    extern __shared__ char smc[];
    const long long sX = (long long)LSEQ * DDIM;
    const long long sT = (long long)DDIM * LSEQ;
    const long long sS = (long long)LSEQ * LSEQ;
    gemm_body<3>(A2, XmT, out1, LSEQ, DDIM, LSEQ, sS, sT, sX, nullptr, nullptr, 0.f,
                 blockIdx.z, blockIdx.y * 128, blockIdx.x * 256, smc);
}

// ---------------- fp32 -> fp16 conversion of external GEMM inputs ----------------
__global__ __launch_bounds__(256)
void cvt_h(const float4* __restrict__ in, __half2* __restrict__ out, int n4)
{
    const int i = blockIdx.x * 256 + threadIdx.x;
    if (i < n4) {
        float4 v = in[i];
        out[2 * i]     = __floats2half2_rn(v.x, v.y);
        out[2 * i + 1] = __floats2half2_rn(v.z, v.w);
    }
}

// ---------------- softmax (no max-subtraction; logits are O(10), masked = -1e30 -> exp = 0) --------
__global__ __launch_bounds__(256)
void zero_k(float* __restrict__ p, int n)
{
    const int i = blockIdx.x * 256 + threadIdx.x;
    if (i < n) p[i] = 0.0f;
}

__global__ __launch_bounds__(256)
void sums_k(const float* __restrict__ S, float* __restrict__ rowsum, float* __restrict__ colsum)
{
    __shared__ float rp[128][9];
    const int z = blockIdx.y, slab = blockIdx.x;
    const float* Sb = S + (long long)z * LSEQ * LSEQ + (long long)slab * 128 * LSEQ;
    const int t = threadIdx.x, w = t >> 5, ln = t & 31;
    float colacc[8] = {0, 0, 0, 0, 0, 0, 0, 0};
#pragma unroll 1
    for (int r = 0; r < 128; ++r) {
        const float* pr = Sb + (long long)r * LSEQ;
        float part = 0.0f;
#pragma unroll
        for (int j = 0; j < 8; ++j) {
            const float e = expf(pr[t + 256 * j]);
            part += e;
            colacc[j] += e;
        }
#pragma unroll
        for (int o = 16; o; o >>= 1) part += __shfl_xor_sync(0xffffffffu, part, o);
        if (ln == 0) rp[r][w] = part;
    }
    __syncthreads();
    if (t < 128) {
        float s = 0.0f;
#pragma unroll
        for (int j = 0; j < 8; ++j) s += rp[t][j];
        rowsum[z * LSEQ + slab * 128 + t] = s;
    }
#pragma unroll
    for (int j = 0; j < 8; ++j)
        atomicAdd(&colsum[z * LSEQ + t + 256 * j], colacc[j]);
}

__global__ __launch_bounds__(256)
void writeout_k(const float* __restrict__ S, __half* __restrict__ A2, __half* __restrict__ A1T,
                const float* __restrict__ rowsum, const float* __restrict__ colsum)
{
    __shared__ float tb[32][33];
    const int z = blockIdx.z;
    const int x0 = blockIdx.x * 32;  // m
    const int y0 = blockIdx.y * 32;  // l
    const int tx = threadIdx.x, ty = threadIdx.y;
    const long long sS = (long long)LSEQ * LSEQ;
    const float* Sb = S + (long long)z * sS;
#pragma unroll
    for (int r = 0; r < 4; ++r) {
        const int l = y0 + ty + r * 8;
        const float e = expf(Sb[(long long)l * LSEQ + x0 + tx]);
        tb[ty + r * 8][tx] = e;
        const float rs = rowsum[z * LSEQ + l];
        const float rr = rs > 0.0f ? 1.0f / rs : 0.0f;
        A2[(long long)z * sS + (long long)l * LSEQ + x0 + tx] = __float2half_rn(e * rr);
    }
    __syncthreads();
#pragma unroll
    for (int r = 0; r < 4; ++r) {
        const int m = x0 + ty + r * 8;
        const int l = y0 + tx;
        const float cs = colsum[z * LSEQ + m];
        const float rc = cs > 0.0f ? 1.0f / cs : 0.0f;
        A1T[(long long)z * sS + (long long)m * LSEQ + l] = __float2half_rn(tb[tx][ty + r * 8] * rc);
    }
}

// ---------------- launcher ----------------
extern "C" void kernel_launch(void* const* d_in, const int* in_sizes, int n_in,
                              void* d_out, int out_size)
{
    const float* x1   = (const float*)d_in[0];
    const float* x2   = (const float*)d_in[1];
    const float* mask = (const float*)d_in[2];
    const float* Wq   = (const float*)d_in[3];
    const float* bq   = (const float*)d_in[4];
    const float* Wk   = (const float*)d_in[5];
    const float* bk   = (const float*)d_in[6];
    const float* Wv   = (const float*)d_in[7];
    const float* bv   = (const float*)d_in[8];

    float* out1 = (float*)d_out;
    float* out2 = out1 + (long long)BATCH * LSEQ * DDIM;

    __half *Qh, *Kh, *V1T, *V2T, *XmT, *A1T, *A2h, *x1h, *x2h, *Wqh, *Wkh, *Wvh;
    float *S, *rowsum, *colsum;
    cudaGetSymbolAddress((void**)&Qh,     g_Qh);
    cudaGetSymbolAddress((void**)&Kh,     g_Kh);
    cudaGetSymbolAddress((void**)&V1T,    g_V1T);
    cudaGetSymbolAddress((void**)&V2T,    g_V2T);
    cudaGetSymbolAddress((void**)&XmT,    g_XmT);
    cudaGetSymbolAddress((void**)&S,      g_S);
    cudaGetSymbolAddress((void**)&A1T,    g_A1T);
    cudaGetSymbolAddress((void**)&A2h,    g_A2h);
    cudaGetSymbolAddress((void**)&rowsum, g_rowsum);
    cudaGetSymbolAddress((void**)&colsum, g_colsum);
    cudaGetSymbolAddress((void**)&x1h,    g_x1h);
    cudaGetSymbolAddress((void**)&x2h,    g_x2h);
    cudaGetSymbolAddress((void**)&Wqh,    g_Wqh);
    cudaGetSymbolAddress((void**)&Wkh,    g_Wkh);
    cudaGetSymbolAddress((void**)&Wvh,    g_Wvh);

    cudaFuncSetAttribute(proj_dual_k,  cudaFuncAttributeMaxDynamicSharedMemorySize, SMEM_TOTAL);
    cudaFuncSetAttribute(sgemm_k,      cudaFuncAttributeMaxDynamicSharedMemorySize, SMEM_TOTAL);
    cudaFuncSetAttribute(apply_dual_k, cudaFuncAttributeMaxDynamicSharedMemorySize, SMEM_TOTAL);
    cudaFuncSetAttribute(final_k,      cudaFuncAttributeMaxDynamicSharedMemorySize, SMEM_TOTAL);

    const float scale = 0.03125f;  // 1/sqrt(1024)

    // convert external inputs to fp16
    {
        const int nX4 = (int)((long long)BATCH * LSEQ * DDIM / 4);
        const int nW4 = DDIM * DDIM / 4;
        cvt_h<<<(nX4 + 255) / 256, 256>>>((const float4*)x1, (__half2*)x1h, nX4);
        cvt_h<<<(nX4 + 255) / 256, 256>>>((const float4*)x2, (__half2*)x2h, nX4);
        cvt_h<<<(nW4 + 255) / 256, 256>>>((const float4*)Wq, (__half2*)Wqh, nW4);
        cvt_h<<<(nW4 + 255) / 256, 256>>>((const float4*)Wk, (__half2*)Wkh, nW4);
        cvt_h<<<(nW4 + 255) / 256, 256>>>((const float4*)Wv, (__half2*)Wvh, nW4);
    }

    dim3 blk(NTHREADS);

    // merged projections: x1 -> {Q (Wq), V1T (Wv)}; x2 -> {K (Wk), V2T (Wv)}
    proj_dual_k<<<dim3(8, 16, 8), blk, SMEM_TOTAL>>>(x1h, Wqh, Wvh, Qh, V1T, bq, bv);
    proj_dual_k<<<dim3(8, 16, 8), blk, SMEM_TOTAL>>>(x2h, Wkh, Wvh, Kh, V2T, bk, bv);

    // logits with scale + additive mask (fp32)
    sgemm_k<<<dim3(8, 16, 8), blk, SMEM_TOTAL>>>(Qh, Kh, S, mask, scale);

    // softmax sums + writeout (both directions, no max-subtraction)
    zero_k<<<(BATCH * LSEQ + 255) / 256, 256>>>(colsum, BATCH * LSEQ);
    sums_k<<<dim3(16, BATCH), blk>>>(S, rowsum, colsum);
    writeout_k<<<dim3(LSEQ / 32, LSEQ / 32, BATCH), dim3(32, 8)>>>(S, A2h, A1T, rowsum, colsum);

    // merged apply: x2_out = A2 @ V2  |  x1_mid^T = (A1^T @ V1) * mask
    apply_dual_k<<<dim3(4, 16, 16), blk, SMEM_TOTAL>>>(A2h, A1T, V2T, V1T, out2, XmT, mask);

    // x1_out = A2 @ x1_mid
    final_k<<<dim3(4, 16, 8), blk, SMEM_TOTAL>>>(A2h, XmT, out1);
}

// round 9
// speedup vs baseline: 3.0452x; 1.1080x over previous
#include <cuda_runtime.h>
#include <cuda_fp16.h>
#include <math.h>
#include <stdint.h>

// Problem constants
#define BATCH 8
#define LSEQ  2048
#define DDIM  1024
#define NEGF  (-1e30f)

// GEMM tiling: CTA 128(M) x 256(N) x 64(K halves), 8 warps as 2(m) x 4(n), warp tile 64x64
#define NTHREADS 256
#define STAGES 3
#define ROW_BYTES 144                       // 64 halves (128B) + 16B pad
#define A_BYTES (128 * ROW_BYTES)           // 18432
#define B_BYTES (256 * ROW_BYTES)           // 36864
#define STAGE_BYTES (A_BYTES + B_BYTES)     // 55296
#define SMEM_TOTAL (STAGES * STAGE_BYTES)   // 165888

// ---------------- scratch (device globals; no allocation allowed) ----------------
__device__ __half g_Qh [(size_t)BATCH * LSEQ * DDIM];
__device__ __half g_Kh [(size_t)BATCH * LSEQ * DDIM];
__device__ __half g_V1T[(size_t)BATCH * DDIM * LSEQ];
__device__ __half g_V2T[(size_t)BATCH * DDIM * LSEQ];
__device__ __half g_XmT[(size_t)BATCH * DDIM * LSEQ];
__device__ __half g_Eh [(size_t)BATCH * LSEQ * LSEQ];   // exp(logits), half
__device__ __half g_A1T[(size_t)BATCH * LSEQ * LSEQ];
__device__ __half g_A2h[(size_t)BATCH * LSEQ * LSEQ];
__device__ float  g_rowsum[BATCH * LSEQ];
__device__ float  g_colsum[BATCH * LSEQ];
__device__ __half g_x1h[(size_t)BATCH * LSEQ * DDIM];
__device__ __half g_x2h[(size_t)BATCH * LSEQ * DDIM];
__device__ __half g_Wqh[(size_t)DDIM * DDIM];
__device__ __half g_Wkh[(size_t)DDIM * DDIM];
__device__ __half g_Wvh[(size_t)DDIM * DDIM];

// ---------------- helpers ----------------
__device__ __forceinline__ uint32_t smem_to_u32(const void* p) {
    uint32_t a;
    asm("{ .reg .u64 t; cvta.to.shared.u64 t, %1; cvt.u32.u64 %0, t; }" : "=r"(a) : "l"(p));
    return a;
}

#define CP_ASYNC16(dst, src) \
    asm volatile("cp.async.cg.shared.global [%0], [%1], 16;" :: "r"(dst), "l"(src) : "memory")
#define CP_COMMIT() asm volatile("cp.async.commit_group;" ::: "memory")

#define LDSM_X4(r, addr) \
    asm volatile("ldmatrix.sync.aligned.m8n8.x4.shared.b16 {%0,%1,%2,%3}, [%4];" \
        : "=r"((r)[0]), "=r"((r)[1]), "=r"((r)[2]), "=r"((r)[3]) : "r"(addr))

// m16n8k16 fp16 MMA, fp32 accumulate
#define MMA_F16(d, a, b)                                                   \
    asm volatile(                                                          \
        "mma.sync.aligned.m16n8k16.row.col.f32.f16.f16.f32 "               \
        "{%0,%1,%2,%3}, {%4,%5,%6,%7}, {%8,%9}, {%0,%1,%2,%3};"            \
        : "+f"(d[0]), "+f"(d[1]), "+f"(d[2]), "+f"(d[3])                   \
        : "r"(a[0]), "r"(a[1]), "r"(a[2]), "r"(a[3]), "r"(b[0]), "r"(b[1]))

// ---------------------------------------------------------------------------
// NT GEMM body: C[m,n] = sum_k A[m,k]*B[n,k]; A,B __half [rows, K] k-contig.
// MODE 0: +bias[n], HALF out, normal store
// MODE 1: +bias[n], HALF out, transposed store C[n,m]
// MODE 2: e=__expf(acc*scale+(1-mask[z,n])*NEG), HALF out + atomic row/col sums
// MODE 3: plain FLOAT out, normal store
// MODE 4: *mask[z,m], HALF out, transposed store C[n,m]
// ---------------------------------------------------------------------------
template <int MODE>
__device__ __forceinline__
void gemm_body(const __half* __restrict__ A, const __half* __restrict__ B, void* __restrict__ Cv,
               int M, int N, int K, long long sA, long long sB, long long sC,
               const float* __restrict__ bias, const float* __restrict__ mask, float scale,
               int z, int m0, int n0, char* smc)
{
    const uint32_t smem_u = smem_to_u32(smc);
    const int tid = threadIdx.x, wid = tid >> 5, lane = tid & 31;
    const int wm = wid & 1, wn = wid >> 1;      // 2 x 4 warps
    const int g = lane >> 2, tg = lane & 3;

    const __half* Abase = A + (long long)z * sA + (long long)m0 * K;
    const __half* Bbase = B + (long long)z * sB + (long long)n0 * K;
    const int T = K >> 6;                       // 64 halves per k-tile

    // cp.async staging: rows of 64 halves = 128B = 8 chunks of 16B
    const int sr = tid >> 3;                    // 0..31
    const int sj = tid & 7;                     // chunk 0..7
    auto stage = [&](int u) {
        const int s = u % STAGES;
        const uint32_t sa = smem_u + s * STAGE_BYTES;
        const uint32_t sb = sa + A_BYTES;
        const __half* Asrc = Abase + (size_t)u * 64 + sj * 8;
        const __half* Bsrc = Bbase + (size_t)u * 64 + sj * 8;
        const uint32_t dw = sj * 16;
#pragma unroll
        for (int i = 0; i < 4; ++i) {
            const int r = sr + i * 32;
            CP_ASYNC16(sa + r * ROW_BYTES + dw, Asrc + (size_t)r * K);
        }
#pragma unroll
        for (int i = 0; i < 8; ++i) {
            const int r = sr + i * 32;
            CP_ASYNC16(sb + r * ROW_BYTES + dw, Bsrc + (size_t)r * K);
        }
        CP_COMMIT();
    };

    float acc[4][8][4];
#pragma unroll
    for (int a = 0; a < 4; ++a)
#pragma unroll
        for (int b = 0; b < 8; ++b)
#pragma unroll
            for (int c = 0; c < 4; ++c) acc[a][b][c] = 0.0f;

    stage(0);
    stage(1);

    // ldmatrix per-thread address offsets (bytes)
    const uint32_t a_lm = (uint32_t)((wm * 64 + (lane & 15)) * ROW_BYTES + (lane >> 4) * 16);
    const uint32_t b_lm = (uint32_t)((wn * 64 + ((lane >> 4) << 3) + (lane & 7)) * ROW_BYTES +
                                     ((lane >> 3) & 1) * 16);

    for (int t = 0; t < T; ++t) {
        if (t < T - 1) asm volatile("cp.async.wait_group 1;" ::: "memory");
        else           asm volatile("cp.async.wait_group 0;" ::: "memory");
        __syncthreads();

        if (t + 2 < T) stage(t + 2);

        const uint32_t sbase = smem_u + (t % STAGES) * STAGE_BYTES;
#pragma unroll
        for (int ks = 0; ks < 4; ++ks) {        // 4 k16 steps per 64-half tile
            const uint32_t abase = sbase + a_lm + ks * 32;
            const uint32_t bbase = sbase + A_BYTES + b_lm + ks * 32;
            uint32_t af[4][4], bf[4][4];
#pragma unroll
            for (int mt = 0; mt < 4; ++mt) LDSM_X4(af[mt], abase + mt * (16 * ROW_BYTES));
#pragma unroll
            for (int np = 0; np < 4; ++np) LDSM_X4(bf[np], bbase + np * (16 * ROW_BYTES));
#pragma unroll
            for (int mt = 0; mt < 4; ++mt)
#pragma unroll
                for (int nt = 0; nt < 8; ++nt)
                    MMA_F16(acc[mt][nt], af[mt], (bf[nt >> 1] + (nt & 1) * 2));
        }
    }

    // ---------------- epilogue ----------------
    if (MODE == 0) {
        __half* Cb = (__half*)Cv + (long long)z * sC;
#pragma unroll
        for (int mt = 0; mt < 4; ++mt)
#pragma unroll
            for (int nt = 0; nt < 8; ++nt) {
                const int mA = m0 + wm * 64 + mt * 16 + g;
                const int n  = n0 + wn * 64 + nt * 8 + tg * 2;
                const float b0 = bias[n], b1 = bias[n + 1];
                *(__half2*)(Cb + (long long)mA * N + n) =
                    __floats2half2_rn(acc[mt][nt][0] + b0, acc[mt][nt][1] + b1);
                *(__half2*)(Cb + (long long)(mA + 8) * N + n) =
                    __floats2half2_rn(acc[mt][nt][2] + b0, acc[mt][nt][3] + b1);
            }
    } else if (MODE == 2) {
        // exp + half store + fused atomic row/col sums
        __half* Cb = (__half*)Cv + (long long)z * sC;
        float rs[8], cs[16];
#pragma unroll
        for (int i = 0; i < 8; ++i) rs[i] = 0.0f;
#pragma unroll
        for (int i = 0; i < 16; ++i) cs[i] = 0.0f;
#pragma unroll
        for (int mt = 0; mt < 4; ++mt)
#pragma unroll
            for (int nt = 0; nt < 8; ++nt) {
                const int mA = m0 + wm * 64 + mt * 16 + g;
                const int n  = n0 + wn * 64 + nt * 8 + tg * 2;
                const float mb0 = (1.0f - mask[(long long)z * N + n]) * NEGF;
                const float mb1 = (1.0f - mask[(long long)z * N + n + 1]) * NEGF;
                const float e0 = __expf(acc[mt][nt][0] * scale + mb0);
                const float e1 = __expf(acc[mt][nt][1] * scale + mb1);
                const float e2 = __expf(acc[mt][nt][2] * scale + mb0);
                const float e3 = __expf(acc[mt][nt][3] * scale + mb1);
                *(__half2*)(Cb + (long long)mA * N + n)       = __floats2half2_rn(e0, e1);
                *(__half2*)(Cb + (long long)(mA + 8) * N + n) = __floats2half2_rn(e2, e3);
                rs[mt * 2]     += e0 + e1;
                rs[mt * 2 + 1] += e2 + e3;
                cs[nt * 2]     += e0 + e2;
                cs[nt * 2 + 1] += e1 + e3;
            }
        // row sums: reduce over tg (lane bits 0-1)
#pragma unroll
        for (int i = 0; i < 8; ++i) {
            rs[i] += __shfl_xor_sync(0xffffffffu, rs[i], 1);
            rs[i] += __shfl_xor_sync(0xffffffffu, rs[i], 2);
        }
        if (tg == 0) {
#pragma unroll
            for (int mt = 0; mt < 4; ++mt) {
                atomicAdd(&g_rowsum[z * LSEQ + m0 + wm * 64 + mt * 16 + g],     rs[mt * 2]);
                atomicAdd(&g_rowsum[z * LSEQ + m0 + wm * 64 + mt * 16 + g + 8], rs[mt * 2 + 1]);
            }
        }
        // col sums: reduce over g (lane bits 2-4)
#pragma unroll
        for (int i = 0; i < 16; ++i) {
            cs[i] += __shfl_xor_sync(0xffffffffu, cs[i], 4);
            cs[i] += __shfl_xor_sync(0xffffffffu, cs[i], 8);
            cs[i] += __shfl_xor_sync(0xffffffffu, cs[i], 16);
        }
        if (g == 0) {
#pragma unroll
            for (int nt = 0; nt < 8; ++nt) {
                atomicAdd(&g_colsum[z * LSEQ + n0 + wn * 64 + nt * 8 + tg * 2],     cs[nt * 2]);
                atomicAdd(&g_colsum[z * LSEQ + n0 + wn * 64 + nt * 8 + tg * 2 + 1], cs[nt * 2 + 1]);
            }
        }
    } else if (MODE == 3) {
        float* Cb = (float*)Cv + (long long)z * sC;
#pragma unroll
        for (int mt = 0; mt < 4; ++mt)
#pragma unroll
            for (int nt = 0; nt < 8; ++nt) {
                const int mA = m0 + wm * 64 + mt * 16 + g;
                const int n  = n0 + wn * 64 + nt * 8 + tg * 2;
                *(float2*)(Cb + (long long)mA * N + n) =
                    make_float2(acc[mt][nt][0], acc[mt][nt][1]);
                *(float2*)(Cb + (long long)(mA + 8) * N + n) =
                    make_float2(acc[mt][nt][2], acc[mt][nt][3]);
            }
    } else {
        // transposed HALF store via smem staging, four 64-col chunks (chunk = wn)
        float* Csh = (float*)smc;   // [128][65]
        __half* Cb = (__half*)Cv + (long long)z * sC;
#pragma unroll 1
        for (int ch = 0; ch < 4; ++ch) {
            __syncthreads();
            if (wn == ch) {
#pragma unroll
                for (int mt = 0; mt < 4; ++mt)
#pragma unroll
                    for (int nt = 0; nt < 8; ++nt) {
                        const int ml = wm * 64 + mt * 16 + g;
                        const int nl = nt * 8 + tg * 2;
                        float v0 = acc[mt][nt][0], v1 = acc[mt][nt][1];
                        float v2 = acc[mt][nt][2], v3 = acc[mt][nt][3];
                        if (MODE == 1) {
                            const float b0 = bias[n0 + ch * 64 + nl];
                            const float b1 = bias[n0 + ch * 64 + nl + 1];
                            v0 += b0; v1 += b1; v2 += b0; v3 += b1;
                        }
                        if (MODE == 4) {
                            const float mk0 = mask[(long long)z * M + m0 + ml];
                            const float mk1 = mask[(long long)z * M + m0 + ml + 8];
                            v0 *= mk0; v1 *= mk0; v2 *= mk1; v3 *= mk1;
                        }
                        Csh[ml * 65 + nl]           = v0;
                        Csh[ml * 65 + nl + 1]       = v1;
                        Csh[(ml + 8) * 65 + nl]     = v2;
                        Csh[(ml + 8) * 65 + nl + 1] = v3;
                    }
            }
            __syncthreads();
#pragma unroll
            for (int i = 0; i < 32; ++i) {
                const int idx = tid + i * 256;
                const int nl = idx >> 7, m = idx & 127;
                Cb[(long long)(n0 + ch * 64 + nl) * M + m0 + m] =
                    __float2half_rn(Csh[m * 65 + nl]);
            }
        }
    }
}

// ---------------- GEMM kernel wrappers ----------------
// All projections in one launch: z<8 -> x1 {Q, V1T}; z>=8 -> x2 {K, V2T}
__global__ __launch_bounds__(NTHREADS, 1)
void proj_all_k(const __half* __restrict__ x1h, const __half* __restrict__ x2h,
                const __half* __restrict__ Wqh, const __half* __restrict__ Wkh,
                const __half* __restrict__ Wvh,
                __half* __restrict__ Qh, __half* __restrict__ Kh,
                __half* __restrict__ V1T, __half* __restrict__ V2T,
                const float* __restrict__ bq, const float* __restrict__ bk,
                const float* __restrict__ bv)
{
    extern __shared__ char smc[];
    const int zz = blockIdx.z, m0 = blockIdx.y * 128, bx = blockIdx.x;
    const long long sX = (long long)LSEQ * DDIM;
    const long long sT = (long long)DDIM * LSEQ;
    if (zz < 8) {
        if (bx < 4)
            gemm_body<0>(x1h, Wqh, Qh,  LSEQ, DDIM, DDIM, sX, 0, sX, bq, nullptr, 0.f, zz, m0, bx * 256, smc);
        else
            gemm_body<1>(x1h, Wvh, V1T, LSEQ, DDIM, DDIM, sX, 0, sT, bv, nullptr, 0.f, zz, m0, (bx - 4) * 256, smc);
    } else {
        const int z = zz - 8;
        if (bx < 4)
            gemm_body<0>(x2h, Wkh, Kh,  LSEQ, DDIM, DDIM, sX, 0, sX, bk, nullptr, 0.f, z, m0, bx * 256, smc);
        else
            gemm_body<1>(x2h, Wvh, V2T, LSEQ, DDIM, DDIM, sX, 0, sT, bv, nullptr, 0.f, z, m0, (bx - 4) * 256, smc);
    }
}

// Logits GEMM with fused exp + row/col sums: E = exp(QK^T*scale + maskbias), half
__global__ __launch_bounds__(NTHREADS, 1)
void sgemm_k(const __half* __restrict__ Q, const __half* __restrict__ Kh,
             __half* __restrict__ E, const float* __restrict__ mask, float scale)
{
    extern __shared__ char smc[];
    const long long sX = (long long)LSEQ * DDIM;
    const long long sS = (long long)LSEQ * LSEQ;
    gemm_body<2>(Q, Kh, E, LSEQ, LSEQ, DDIM, sX, sX, sS, nullptr, mask, scale,
                 blockIdx.z, blockIdx.y * 128, blockIdx.x * 256, smc);
}

__global__ __launch_bounds__(NTHREADS, 1)
void apply_dual_k(const __half* __restrict__ A2, const __half* __restrict__ A1T,
                  const __half* __restrict__ V2T, const __half* __restrict__ V1T,
                  float* __restrict__ out2, __half* __restrict__ XmT,
                  const float* __restrict__ mask)
{
    extern __shared__ char smc[];
    const int m0 = blockIdx.y * 128, n0 = blockIdx.x * 256;
    const long long sX = (long long)LSEQ * DDIM;
    const long long sT = (long long)DDIM * LSEQ;
    const long long sS = (long long)LSEQ * LSEQ;
    if (blockIdx.z < 8)
        gemm_body<3>(A2, V2T, out2, LSEQ, DDIM, LSEQ, sS, sT, sX, nullptr, nullptr, 0.f,
                     blockIdx.z, m0, n0, smc);
    else
        gemm_body<4>(A1T, V1T, XmT, LSEQ, DDIM, LSEQ, sS, sT, sT, nullptr, mask, 0.f,
                     blockIdx.z - 8, m0, n0, smc);
}

__global__ __launch_bounds__(NTHREADS, 1)
void final_k(const __half* __restrict__ A2, const __half* __restrict__ XmT, float* __restrict__ out1)
{
    extern __shared__ char smc[];
    const long long sX = (long long)LSEQ * DDIM;
    const long long sT = (long long)DDIM * LSEQ;
    const long long sS = (long long)LSEQ * LSEQ;
    gemm_body<3>(A2, XmT, out1, LSEQ, DDIM, LSEQ, sS, sT, sX, nullptr, nullptr, 0.f,
                 blockIdx.z, blockIdx.y * 128, blockIdx.x * 256, smc);
}

// ---------------- merged fp32 -> fp16 conversion of all external GEMM inputs ----------------
#define NX4 (BATCH * LSEQ * DDIM / 4)   // 4194304
#define NW4 (DDIM * DDIM / 4)           // 262144
#define CVT_TOTAL (2 * NX4 + 3 * NW4)   // 9175040

__global__ __launch_bounds__(256)
void cvt_all_k(const float4* __restrict__ x1, const float4* __restrict__ x2,
               const float4* __restrict__ Wq, const float4* __restrict__ Wk,
               const float4* __restrict__ Wv,
               __half2* __restrict__ x1h, __half2* __restrict__ x2h,
               __half2* __restrict__ Wqh, __half2* __restrict__ Wkh,
               __half2* __restrict__ Wvh)
{
    int i = blockIdx.x * 256 + threadIdx.x;
    if (i >= CVT_TOTAL) return;
    const float4* src;
    __half2* dst;
    if (i < NX4)               { src = x1; dst = x1h; }
    else if (i < 2 * NX4)      { src = x2; dst = x2h; i -= NX4; }
    else if (i < 2 * NX4 + NW4)     { src = Wq; dst = Wqh; i -= 2 * NX4; }
    else if (i < 2 * NX4 + 2 * NW4) { src = Wk; dst = Wkh; i -= 2 * NX4 + NW4; }
    else                            { src = Wv; dst = Wvh; i -= 2 * NX4 + 2 * NW4; }
    const float4 v = src[i];
    dst[2 * i]     = __floats2half2_rn(v.x, v.y);
    dst[2 * i + 1] = __floats2half2_rn(v.z, v.w);
}

// ---------------- zero row/col sums ----------------
__global__ __launch_bounds__(256)
void zero2_k()
{
    const int i = blockIdx.x * 256 + threadIdx.x;
    if (i < BATCH * LSEQ) {
        g_rowsum[i] = 0.0f;
        g_colsum[i] = 0.0f;
    }
}

// ---------------- writeout: A2h[l,m] = e/rowsum[l]; A1T[m,l] = e/colsum[m] ----------------
__global__ __launch_bounds__(256)
void writeout_k(const __half* __restrict__ E, __half* __restrict__ A2, __half* __restrict__ A1T)
{
    __shared__ float tb[32][33];
    const int z = blockIdx.z;
    const int x0 = blockIdx.x * 32;  // m
    const int y0 = blockIdx.y * 32;  // l
    const int tx = threadIdx.x, ty = threadIdx.y;
    const long long sS = (long long)LSEQ * LSEQ;
    const __half* Eb = E + (long long)z * sS;
#pragma unroll
    for (int r = 0; r < 4; ++r) {
        const int l = y0 + ty + r * 8;
        const float e = __half2float(Eb[(long long)l * LSEQ + x0 + tx]);
        tb[ty + r * 8][tx] = e;
        const float rs = g_rowsum[z * LSEQ + l];
        const float rr = rs > 0.0f ? 1.0f / rs : 0.0f;
        A2[(long long)z * sS + (long long)l * LSEQ + x0 + tx] = __float2half_rn(e * rr);
    }
    __syncthreads();
#pragma unroll
    for (int r = 0; r < 4; ++r) {
        const int m = x0 + ty + r * 8;
        const int l = y0 + tx;
        const float cs = g_colsum[z * LSEQ + m];
        const float rc = cs > 0.0f ? 1.0f / cs : 0.0f;
        A1T[(long long)z * sS + (long long)m * LSEQ + l] = __float2half_rn(tb[tx][ty + r * 8] * rc);
    }
}

// ---------------- launcher ----------------
extern "C" void kernel_launch(void* const* d_in, const int* in_sizes, int n_in,
                              void* d_out, int out_size)
{
    const float* x1   = (const float*)d_in[0];
    const float* x2   = (const float*)d_in[1];
    const float* mask = (const float*)d_in[2];
    const float* Wq   = (const float*)d_in[3];
    const float* bq   = (const float*)d_in[4];
    const float* Wk   = (const float*)d_in[5];
    const float* bk   = (const float*)d_in[6];
    const float* Wv   = (const float*)d_in[7];
    const float* bv   = (const float*)d_in[8];

    float* out1 = (float*)d_out;
    float* out2 = out1 + (long long)BATCH * LSEQ * DDIM;

    __half *Qh, *Kh, *V1T, *V2T, *XmT, *Eh, *A1T, *A2h, *x1h, *x2h, *Wqh, *Wkh, *Wvh;
    cudaGetSymbolAddress((void**)&Qh,  g_Qh);
    cudaGetSymbolAddress((void**)&Kh,  g_Kh);
    cudaGetSymbolAddress((void**)&V1T, g_V1T);
    cudaGetSymbolAddress((void**)&V2T, g_V2T);
    cudaGetSymbolAddress((void**)&XmT, g_XmT);
    cudaGetSymbolAddress((void**)&Eh,  g_Eh);
    cudaGetSymbolAddress((void**)&A1T, g_A1T);
    cudaGetSymbolAddress((void**)&A2h, g_A2h);
    cudaGetSymbolAddress((void**)&x1h, g_x1h);
    cudaGetSymbolAddress((void**)&x2h, g_x2h);
    cudaGetSymbolAddress((void**)&Wqh, g_Wqh);
    cudaGetSymbolAddress((void**)&Wkh, g_Wkh);
    cudaGetSymbolAddress((void**)&Wvh, g_Wvh);

    cudaFuncSetAttribute(proj_all_k,   cudaFuncAttributeMaxDynamicSharedMemorySize, SMEM_TOTAL);
    cudaFuncSetAttribute(sgemm_k,      cudaFuncAttributeMaxDynamicSharedMemorySize, SMEM_TOTAL);
    cudaFuncSetAttribute(apply_dual_k, cudaFuncAttributeMaxDynamicSharedMemorySize, SMEM_TOTAL);
    cudaFuncSetAttribute(final_k,      cudaFuncAttributeMaxDynamicSharedMemorySize, SMEM_TOTAL);

    const float scale = 0.03125f;  // 1/sqrt(1024)

    dim3 blk(NTHREADS);

    // convert all external inputs to fp16 (single launch) + zero sums
    cvt_all_k<<<(CVT_TOTAL + 255) / 256, 256>>>((const float4*)x1, (const float4*)x2,
                                                (const float4*)Wq, (const float4*)Wk,
                                                (const float4*)Wv,
                                                (__half2*)x1h, (__half2*)x2h,
                                                (__half2*)Wqh, (__half2*)Wkh, (__half2*)Wvh);
    zero2_k<<<(BATCH * LSEQ + 255) / 256, 256>>>();

    // all projections: x1 -> {Q, V1T}; x2 -> {K, V2T}
    proj_all_k<<<dim3(8, 16, 16), blk, SMEM_TOTAL>>>(x1h, x2h, Wqh, Wkh, Wvh,
                                                     Qh, Kh, V1T, V2T, bq, bk, bv);

    // logits GEMM with fused exp + row/col sums (half E out)
    sgemm_k<<<dim3(8, 16, 8), blk, SMEM_TOTAL>>>(Qh, Kh, Eh, mask, scale);

    // normalize both directions (reads half E, writes A2h + transposed A1T)
    writeout_k<<<dim3(LSEQ / 32, LSEQ / 32, BATCH), dim3(32, 8)>>>(Eh, A2h, A1T);

    // merged apply: x2_out = A2 @ V2  |  x1_mid^T = (A1^T @ V1) * mask
    apply_dual_k<<<dim3(4, 16, 16), blk, SMEM_TOTAL>>>(A2h, A1T, V2T, V1T, out2, XmT, mask);

    // x1_out = A2 @ x1_mid
    final_k<<<dim3(4, 16, 8), blk, SMEM_TOTAL>>>(A2h, XmT, out1);
}

// round 10
// speedup vs baseline: 3.4371x; 1.1287x over previous
#include <cuda_runtime.h>
#include <cuda_fp16.h>
#include <math.h>
#include <stdint.h>

// Problem constants
#define BATCH 8
#define LSEQ  2048
#define DDIM  1024
#define NEGF  (-1e30f)

// GEMM tiling: CTA 128(M) x 128(N) x 64(K halves), 8 warps as 2(m) x 4(n), warp tile 64x32
// 2 CTAs per SM (regs capped to 128, smem 110.6KB/CTA)
#define NTHREADS 256
#define STAGES 3
#define ROW_BYTES 144                       // 64 halves (128B) + 16B pad
#define A_BYTES (128 * ROW_BYTES)           // 18432
#define B_BYTES (128 * ROW_BYTES)           // 18432
#define STAGE_BYTES (A_BYTES + B_BYTES)     // 36864
#define SMEM_TOTAL (STAGES * STAGE_BYTES)   // 110592

// ---------------- scratch (device globals; no allocation allowed) ----------------
__device__ __half g_Qh [(size_t)BATCH * LSEQ * DDIM];
__device__ __half g_Kh [(size_t)BATCH * LSEQ * DDIM];
__device__ __half g_V1T[(size_t)BATCH * DDIM * LSEQ];
__device__ __half g_V2T[(size_t)BATCH * DDIM * LSEQ];
__device__ __half g_XmT[(size_t)BATCH * DDIM * LSEQ];
__device__ __half g_Eh [(size_t)BATCH * LSEQ * LSEQ];   // exp(logits), half
__device__ __half g_A1T[(size_t)BATCH * LSEQ * LSEQ];
__device__ __half g_A2h[(size_t)BATCH * LSEQ * LSEQ];
__device__ float  g_rowsum[BATCH * LSEQ];
__device__ float  g_colsum[BATCH * LSEQ];
__device__ __half g_x1h[(size_t)BATCH * LSEQ * DDIM];
__device__ __half g_x2h[(size_t)BATCH * LSEQ * DDIM];
__device__ __half g_Wqh[(size_t)DDIM * DDIM];
__device__ __half g_Wkh[(size_t)DDIM * DDIM];
__device__ __half g_Wvh[(size_t)DDIM * DDIM];

// ---------------- helpers ----------------
__device__ __forceinline__ uint32_t smem_to_u32(const void* p) {
    uint32_t a;
    asm("{ .reg .u64 t; cvta.to.shared.u64 t, %1; cvt.u32.u64 %0, t; }" : "=r"(a) : "l"(p));
    return a;
}

#define CP_ASYNC16(dst, src) \
    asm volatile("cp.async.cg.shared.global [%0], [%1], 16;" :: "r"(dst), "l"(src) : "memory")
#define CP_COMMIT() asm volatile("cp.async.commit_group;" ::: "memory")

#define LDSM_X4(r, addr) \
    asm volatile("ldmatrix.sync.aligned.m8n8.x4.shared.b16 {%0,%1,%2,%3}, [%4];" \
        : "=r"((r)[0]), "=r"((r)[1]), "=r"((r)[2]), "=r"((r)[3]) : "r"(addr))

// m16n8k16 fp16 MMA, fp32 accumulate
#define MMA_F16(d, a, b)                                                   \
    asm volatile(                                                          \
        "mma.sync.aligned.m16n8k16.row.col.f32.f16.f16.f32 "               \
        "{%0,%1,%2,%3}, {%4,%5,%6,%7}, {%8,%9}, {%0,%1,%2,%3};"            \
        : "+f"(d[0]), "+f"(d[1]), "+f"(d[2]), "+f"(d[3])                   \
        : "r"(a[0]), "r"(a[1]), "r"(a[2]), "r"(a[3]), "r"(b[0]), "r"(b[1]))

// ---------------------------------------------------------------------------
// NT GEMM body: C[m,n] = sum_k A[m,k]*B[n,k]; A,B __half [rows, K] k-contig.
// CTA tile 128x128x64. Warp tile 64x32.
// MODE 0: +bias[n], HALF out, normal store
// MODE 1: +bias[n], HALF out, transposed store C[n,m]
// MODE 2: e=__expf(acc*scale+(1-mask[z,n])*NEG), HALF out + atomic row/col sums
// MODE 3: plain FLOAT out, normal store
// MODE 4: *mask[z,m], HALF out, transposed store C[n,m]
// ---------------------------------------------------------------------------
template <int MODE>
__device__ __forceinline__
void gemm_body(const __half* __restrict__ A, const __half* __restrict__ B, void* __restrict__ Cv,
               int M, int N, int K, long long sA, long long sB, long long sC,
               const float* __restrict__ bias, const float* __restrict__ mask, float scale,
               int z, int m0, int n0, char* smc)
{
    const uint32_t smem_u = smem_to_u32(smc);
    const int tid = threadIdx.x, wid = tid >> 5, lane = tid & 31;
    const int wm = wid & 1, wn = wid >> 1;      // 2 x 4 warps, warp tile 64(m) x 32(n)
    const int g = lane >> 2, tg = lane & 3;

    const __half* Abase = A + (long long)z * sA + (long long)m0 * K;
    const __half* Bbase = B + (long long)z * sB + (long long)n0 * K;
    const int T = K >> 6;                       // 64 halves per k-tile

    // cp.async staging: 128 rows A + 128 rows B, rows of 64 halves = 128B = 8 chunks of 16B
    const int sr = tid >> 3;                    // 0..31
    const int sj = tid & 7;                     // chunk 0..7
    auto stage = [&](int u) {
        const int s = u % STAGES;
        const uint32_t sa = smem_u + s * STAGE_BYTES;
        const uint32_t sb = sa + A_BYTES;
        const __half* Asrc = Abase + (size_t)u * 64 + sj * 8;
        const __half* Bsrc = Bbase + (size_t)u * 64 + sj * 8;
        const uint32_t dw = sj * 16;
#pragma unroll
        for (int i = 0; i < 4; ++i) {
            const int r = sr + i * 32;
            CP_ASYNC16(sa + r * ROW_BYTES + dw, Asrc + (size_t)r * K);
        }
#pragma unroll
        for (int i = 0; i < 4; ++i) {
            const int r = sr + i * 32;
            CP_ASYNC16(sb + r * ROW_BYTES + dw, Bsrc + (size_t)r * K);
        }
        CP_COMMIT();
    };

    float acc[4][4][4];
#pragma unroll
    for (int a = 0; a < 4; ++a)
#pragma unroll
        for (int b = 0; b < 4; ++b)
#pragma unroll
            for (int c = 0; c < 4; ++c) acc[a][b][c] = 0.0f;

    stage(0);
    stage(1);

    // ldmatrix per-thread address offsets (bytes)
    const uint32_t a_lm = (uint32_t)((wm * 64 + (lane & 15)) * ROW_BYTES + (lane >> 4) * 16);
    const uint32_t b_lm = (uint32_t)((wn * 32 + ((lane >> 4) << 3) + (lane & 7)) * ROW_BYTES +
                                     ((lane >> 3) & 1) * 16);

    for (int t = 0; t < T; ++t) {
        if (t < T - 1) asm volatile("cp.async.wait_group 1;" ::: "memory");
        else           asm volatile("cp.async.wait_group 0;" ::: "memory");
        __syncthreads();

        if (t + 2 < T) stage(t + 2);

        const uint32_t sbase = smem_u + (t % STAGES) * STAGE_BYTES;
#pragma unroll
        for (int ks = 0; ks < 4; ++ks) {        // 4 k16 steps per 64-half tile
            const uint32_t abase = sbase + a_lm + ks * 32;
            const uint32_t bbase = sbase + A_BYTES + b_lm + ks * 32;
            uint32_t af[4][4], bf[2][4];
#pragma unroll
            for (int mt = 0; mt < 4; ++mt) LDSM_X4(af[mt], abase + mt * (16 * ROW_BYTES));
#pragma unroll
            for (int np = 0; np < 2; ++np) LDSM_X4(bf[np], bbase + np * (16 * ROW_BYTES));
#pragma unroll
            for (int mt = 0; mt < 4; ++mt)
#pragma unroll
                for (int nt = 0; nt < 4; ++nt)
                    MMA_F16(acc[mt][nt], af[mt], (bf[nt >> 1] + (nt & 1) * 2));
        }
    }

    // ---------------- epilogue ----------------
    if (MODE == 0) {
        __half* Cb = (__half*)Cv + (long long)z * sC;
#pragma unroll
        for (int mt = 0; mt < 4; ++mt)
#pragma unroll
            for (int nt = 0; nt < 4; ++nt) {
                const int mA = m0 + wm * 64 + mt * 16 + g;
                const int n  = n0 + wn * 32 + nt * 8 + tg * 2;
                const float b0 = bias[n], b1 = bias[n + 1];
                *(__half2*)(Cb + (long long)mA * N + n) =
                    __floats2half2_rn(acc[mt][nt][0] + b0, acc[mt][nt][1] + b1);
                *(__half2*)(Cb + (long long)(mA + 8) * N + n) =
                    __floats2half2_rn(acc[mt][nt][2] + b0, acc[mt][nt][3] + b1);
            }
    } else if (MODE == 2) {
        // exp + half store + fused atomic row/col sums
        __half* Cb = (__half*)Cv + (long long)z * sC;
        float rs[8], cs[8];
#pragma unroll
        for (int i = 0; i < 8; ++i) { rs[i] = 0.0f; cs[i] = 0.0f; }
#pragma unroll
        for (int mt = 0; mt < 4; ++mt)
#pragma unroll
            for (int nt = 0; nt < 4; ++nt) {
                const int mA = m0 + wm * 64 + mt * 16 + g;
                const int n  = n0 + wn * 32 + nt * 8 + tg * 2;
                const float mb0 = (1.0f - mask[(long long)z * N + n]) * NEGF;
                const float mb1 = (1.0f - mask[(long long)z * N + n + 1]) * NEGF;
                const float e0 = __expf(acc[mt][nt][0] * scale + mb0);
                const float e1 = __expf(acc[mt][nt][1] * scale + mb1);
                const float e2 = __expf(acc[mt][nt][2] * scale + mb0);
                const float e3 = __expf(acc[mt][nt][3] * scale + mb1);
                *(__half2*)(Cb + (long long)mA * N + n)       = __floats2half2_rn(e0, e1);
                *(__half2*)(Cb + (long long)(mA + 8) * N + n) = __floats2half2_rn(e2, e3);
                rs[mt * 2]     += e0 + e1;
                rs[mt * 2 + 1] += e2 + e3;
                cs[nt * 2]     += e0 + e2;
                cs[nt * 2 + 1] += e1 + e3;
            }
        // row sums: reduce over tg (lane bits 0-1)
#pragma unroll
        for (int i = 0; i < 8; ++i) {
            rs[i] += __shfl_xor_sync(0xffffffffu, rs[i], 1);
            rs[i] += __shfl_xor_sync(0xffffffffu, rs[i], 2);
        }
        if (tg == 0) {
#pragma unroll
            for (int mt = 0; mt < 4; ++mt) {
                atomicAdd(&g_rowsum[z * LSEQ + m0 + wm * 64 + mt * 16 + g],     rs[mt * 2]);
                atomicAdd(&g_rowsum[z * LSEQ + m0 + wm * 64 + mt * 16 + g + 8], rs[mt * 2 + 1]);
            }
        }
        // col sums: reduce over g (lane bits 2-4)
#pragma unroll
        for (int i = 0; i < 8; ++i) {
            cs[i] += __shfl_xor_sync(0xffffffffu, cs[i], 4);
            cs[i] += __shfl_xor_sync(0xffffffffu, cs[i], 8);
            cs[i] += __shfl_xor_sync(0xffffffffu, cs[i], 16);
        }
        if (g == 0) {
#pragma unroll
            for (int nt = 0; nt < 4; ++nt) {
                atomicAdd(&g_colsum[z * LSEQ + n0 + wn * 32 + nt * 8 + tg * 2],     cs[nt * 2]);
                atomicAdd(&g_colsum[z * LSEQ + n0 + wn * 32 + nt * 8 + tg * 2 + 1], cs[nt * 2 + 1]);
            }
        }
    } else if (MODE == 3) {
        float* Cb = (float*)Cv + (long long)z * sC;
#pragma unroll
        for (int mt = 0; mt < 4; ++mt)
#pragma unroll
            for (int nt = 0; nt < 4; ++nt) {
                const int mA = m0 + wm * 64 + mt * 16 + g;
                const int n  = n0 + wn * 32 + nt * 8 + tg * 2;
                *(float2*)(Cb + (long long)mA * N + n) =
                    make_float2(acc[mt][nt][0], acc[mt][nt][1]);
                *(float2*)(Cb + (long long)(mA + 8) * N + n) =
                    make_float2(acc[mt][nt][2], acc[mt][nt][3]);
            }
    } else {
        // transposed HALF store via smem staging, four 32-col chunks (chunk = wn)
        float* Csh = (float*)smc;   // [128][33]
        __half* Cb = (__half*)Cv + (long long)z * sC;
#pragma unroll 1
        for (int ch = 0; ch < 4; ++ch) {
            __syncthreads();
            if (wn == ch) {
#pragma unroll
                for (int mt = 0; mt < 4; ++mt)
#pragma unroll
                    for (int nt = 0; nt < 4; ++nt) {
                        const int ml = wm * 64 + mt * 16 + g;
                        const int nl = nt * 8 + tg * 2;
                        float v0 = acc[mt][nt][0], v1 = acc[mt][nt][1];
                        float v2 = acc[mt][nt][2], v3 = acc[mt][nt][3];
                        if (MODE == 1) {
                            const float b0 = bias[n0 + ch * 32 + nl];
                            const float b1 = bias[n0 + ch * 32 + nl + 1];
                            v0 += b0; v1 += b1; v2 += b0; v3 += b1;
                        }
                        if (MODE == 4) {
                            const float mk0 = mask[(long long)z * M + m0 + ml];
                            const float mk1 = mask[(long long)z * M + m0 + ml + 8];
                            v0 *= mk0; v1 *= mk0; v2 *= mk1; v3 *= mk1;
                        }
                        Csh[ml * 33 + nl]           = v0;
                        Csh[ml * 33 + nl + 1]       = v1;
                        Csh[(ml + 8) * 33 + nl]     = v2;
                        Csh[(ml + 8) * 33 + nl + 1] = v3;
                    }
            }
            __syncthreads();
#pragma unroll
            for (int i = 0; i < 16; ++i) {
                const int idx = tid + i * 256;
                const int nl = idx >> 7, m = idx & 127;
                Cb[(long long)(n0 + ch * 32 + nl) * M + m0 + m] =
                    __float2half_rn(Csh[m * 33 + nl]);
            }
        }
    }
}

// ---------------- GEMM kernel wrappers ----------------
// All projections in one launch: z<8 -> x1 {Q, V1T}; z>=8 -> x2 {K, V2T}
__global__ __launch_bounds__(NTHREADS, 2)
void proj_all_k(const __half* __restrict__ x1h, const __half* __restrict__ x2h,
                const __half* __restrict__ Wqh, const __half* __restrict__ Wkh,
                const __half* __restrict__ Wvh,
                __half* __restrict__ Qh, __half* __restrict__ Kh,
                __half* __restrict__ V1T, __half* __restrict__ V2T,
                const float* __restrict__ bq, const float* __restrict__ bk,
                const float* __restrict__ bv)
{
    extern __shared__ char smc[];
    const int zz = blockIdx.z, m0 = blockIdx.y * 128, bx = blockIdx.x;
    const long long sX = (long long)LSEQ * DDIM;
    const long long sT = (long long)DDIM * LSEQ;
    if (zz < 8) {
        if (bx < 8)
            gemm_body<0>(x1h, Wqh, Qh,  LSEQ, DDIM, DDIM, sX, 0, sX, bq, nullptr, 0.f, zz, m0, bx * 128, smc);
        else
            gemm_body<1>(x1h, Wvh, V1T, LSEQ, DDIM, DDIM, sX, 0, sT, bv, nullptr, 0.f, zz, m0, (bx - 8) * 128, smc);
    } else {
        const int z = zz - 8;
        if (bx < 8)
            gemm_body<0>(x2h, Wkh, Kh,  LSEQ, DDIM, DDIM, sX, 0, sX, bk, nullptr, 0.f, z, m0, bx * 128, smc);
        else
            gemm_body<1>(x2h, Wvh, V2T, LSEQ, DDIM, DDIM, sX, 0, sT, bv, nullptr, 0.f, z, m0, (bx - 8) * 128, smc);
    }
}

// Logits GEMM with fused exp + row/col sums: E = exp(QK^T*scale + maskbias), half
__global__ __launch_bounds__(NTHREADS, 2)
void sgemm_k(const __half* __restrict__ Q, const __half* __restrict__ Kh,
             __half* __restrict__ E, const float* __restrict__ mask, float scale)
{
    extern __shared__ char smc[];
    const long long sX = (long long)LSEQ * DDIM;
    const long long sS = (long long)LSEQ * LSEQ;
    gemm_body<2>(Q, Kh, E, LSEQ, LSEQ, DDIM, sX, sX, sS, nullptr, mask, scale,
                 blockIdx.z, blockIdx.y * 128, blockIdx.x * 128, smc);
}

__global__ __launch_bounds__(NTHREADS, 2)
void apply_dual_k(const __half* __restrict__ A2, const __half* __restrict__ A1T,
                  const __half* __restrict__ V2T, const __half* __restrict__ V1T,
                  float* __restrict__ out2, __half* __restrict__ XmT,
                  const float* __restrict__ mask)
{
    extern __shared__ char smc[];
    const int m0 = blockIdx.y * 128, n0 = blockIdx.x * 128;
    const long long sX = (long long)LSEQ * DDIM;
    const long long sT = (long long)DDIM * LSEQ;
    const long long sS = (long long)LSEQ * LSEQ;
    if (blockIdx.z < 8)
        gemm_body<3>(A2, V2T, out2, LSEQ, DDIM, LSEQ, sS, sT, sX, nullptr, nullptr, 0.f,
                     blockIdx.z, m0, n0, smc);
    else
        gemm_body<4>(A1T, V1T, XmT, LSEQ, DDIM, LSEQ, sS, sT, sT, nullptr, mask, 0.f,
                     blockIdx.z - 8, m0, n0, smc);
}

__global__ __launch_bounds__(NTHREADS, 2)
void final_k(const __half* __restrict__ A2, const __half* __restrict__ XmT, float* __restrict__ out1)
{
    extern __shared__ char smc[];
    const long long sX = (long long)LSEQ * DDIM;
    const long long sT = (long long)DDIM * LSEQ;
    const long long sS = (long long)LSEQ * LSEQ;
    gemm_body<3>(A2, XmT, out1, LSEQ, DDIM, LSEQ, sS, sT, sX, nullptr, nullptr, 0.f,
                 blockIdx.z, blockIdx.y * 128, blockIdx.x * 128, smc);
}

// ---------------- merged fp32 -> fp16 conversion of all external GEMM inputs ----------------
#define NX4 (BATCH * LSEQ * DDIM / 4)   // 4194304
#define NW4 (DDIM * DDIM / 4)           // 262144
#define CVT_TOTAL (2 * NX4 + 3 * NW4)   // 9175040

__global__ __launch_bounds__(256)
void cvt_all_k(const float4* __restrict__ x1, const float4* __restrict__ x2,
               const float4* __restrict__ Wq, const float4* __restrict__ Wk,
               const float4* __restrict__ Wv,
               __half2* __restrict__ x1h, __half2* __restrict__ x2h,
               __half2* __restrict__ Wqh, __half2* __restrict__ Wkh,
               __half2* __restrict__ Wvh)
{
    int i = blockIdx.x * 256 + threadIdx.x;
    if (i >= CVT_TOTAL) return;
    const float4* src;
    __half2* dst;
    if (i < NX4)               { src = x1; dst = x1h; }
    else if (i < 2 * NX4)      { src = x2; dst = x2h; i -= NX4; }
    else if (i < 2 * NX4 + NW4)     { src = Wq; dst = Wqh; i -= 2 * NX4; }
    else if (i < 2 * NX4 + 2 * NW4) { src = Wk; dst = Wkh; i -= 2 * NX4 + NW4; }
    else                            { src = Wv; dst = Wvh; i -= 2 * NX4 + 2 * NW4; }
    const float4 v = src[i];
    dst[2 * i]     = __floats2half2_rn(v.x, v.y);
    dst[2 * i + 1] = __floats2half2_rn(v.z, v.w);
}

// ---------------- zero row/col sums ----------------
__global__ __launch_bounds__(256)
void zero2_k()
{
    const int i = blockIdx.x * 256 + threadIdx.x;
    if (i < BATCH * LSEQ) {
        g_rowsum[i] = 0.0f;
        g_colsum[i] = 0.0f;
    }
}

// ---------------- writeout: A2h[l,m] = e/rowsum[l]; A1T[m,l] = e/colsum[m] ----------------
__global__ __launch_bounds__(256)
void writeout_k(const __half* __restrict__ E, __half* __restrict__ A2, __half* __restrict__ A1T)
{
    __shared__ float tb[32][33];
    const int z = blockIdx.z;
    const int x0 = blockIdx.x * 32;  // m
    const int y0 = blockIdx.y * 32;  // l
    const int tx = threadIdx.x, ty = threadIdx.y;
    const long long sS = (long long)LSEQ * LSEQ;
    const __half* Eb = E + (long long)z * sS;
#pragma unroll
    for (int r = 0; r < 4; ++r) {
        const int l = y0 + ty + r * 8;
        const float e = __half2float(Eb[(long long)l * LSEQ + x0 + tx]);
        tb[ty + r * 8][tx] = e;
        const float rs = g_rowsum[z * LSEQ + l];
        const float rr = rs > 0.0f ? 1.0f / rs : 0.0f;
        A2[(long long)z * sS + (long long)l * LSEQ + x0 + tx] = __float2half_rn(e * rr);
    }
    __syncthreads();
#pragma unroll
    for (int r = 0; r < 4; ++r) {
        const int m = x0 + ty + r * 8;
        const int l = y0 + tx;
        const float cs = g_colsum[z * LSEQ + m];
        const float rc = cs > 0.0f ? 1.0f / cs : 0.0f;
        A1T[(long long)z * sS + (long long)m * LSEQ + l] = __float2half_rn(tb[tx][ty + r * 8] * rc);
    }
}

// ---------------- launcher ----------------
extern "C" void kernel_launch(void* const* d_in, const int* in_sizes, int n_in,
                              void* d_out, int out_size)
{
    const float* x1   = (const float*)d_in[0];
    const float* x2   = (const float*)d_in[1];
    const float* mask = (const float*)d_in[2];
    const float* Wq   = (const float*)d_in[3];
    const float* bq   = (const float*)d_in[4];
    const float* Wk   = (const float*)d_in[5];
    const float* bk   = (const float*)d_in[6];
    const float* Wv   = (const float*)d_in[7];
    const float* bv   = (const float*)d_in[8];

    float* out1 = (float*)d_out;
    float* out2 = out1 + (long long)BATCH * LSEQ * DDIM;

    __half *Qh, *Kh, *V1T, *V2T, *XmT, *Eh, *A1T, *A2h, *x1h, *x2h, *Wqh, *Wkh, *Wvh;
    cudaGetSymbolAddress((void**)&Qh,  g_Qh);
    cudaGetSymbolAddress((void**)&Kh,  g_Kh);
    cudaGetSymbolAddress((void**)&V1T, g_V1T);
    cudaGetSymbolAddress((void**)&V2T, g_V2T);
    cudaGetSymbolAddress((void**)&XmT, g_XmT);
    cudaGetSymbolAddress((void**)&Eh,  g_Eh);
    cudaGetSymbolAddress((void**)&A1T, g_A1T);
    cudaGetSymbolAddress((void**)&A2h, g_A2h);
    cudaGetSymbolAddress((void**)&x1h, g_x1h);
    cudaGetSymbolAddress((void**)&x2h, g_x2h);
    cudaGetSymbolAddress((void**)&Wqh, g_Wqh);
    cudaGetSymbolAddress((void**)&Wkh, g_Wkh);
    cudaGetSymbolAddress((void**)&Wvh, g_Wvh);

    cudaFuncSetAttribute(proj_all_k,   cudaFuncAttributeMaxDynamicSharedMemorySize, SMEM_TOTAL);
    cudaFuncSetAttribute(sgemm_k,      cudaFuncAttributeMaxDynamicSharedMemorySize, SMEM_TOTAL);
    cudaFuncSetAttribute(apply_dual_k, cudaFuncAttributeMaxDynamicSharedMemorySize, SMEM_TOTAL);
    cudaFuncSetAttribute(final_k,      cudaFuncAttributeMaxDynamicSharedMemorySize, SMEM_TOTAL);

    const float scale = 0.03125f;  // 1/sqrt(1024)

    dim3 blk(NTHREADS);

    // convert all external inputs to fp16 (single launch) + zero sums
    cvt_all_k<<<(CVT_TOTAL + 255) / 256, 256>>>((const float4*)x1, (const float4*)x2,
                                                (const float4*)Wq, (const float4*)Wk,
                                                (const float4*)Wv,
                                                (__half2*)x1h, (__half2*)x2h,
                                                (__half2*)Wqh, (__half2*)Wkh, (__half2*)Wvh);
    zero2_k<<<(BATCH * LSEQ + 255) / 256, 256>>>();

    // all projections: x1 -> {Q, V1T}; x2 -> {K, V2T}
    proj_all_k<<<dim3(16, 16, 16), blk, SMEM_TOTAL>>>(x1h, x2h, Wqh, Wkh, Wvh,
                                                      Qh, Kh, V1T, V2T, bq, bk, bv);

    // logits GEMM with fused exp + row/col sums (half E out)
    sgemm_k<<<dim3(16, 16, 8), blk, SMEM_TOTAL>>>(Qh, Kh, Eh, mask, scale);

    // normalize both directions (reads half E, writes A2h + transposed A1T)
    writeout_k<<<dim3(LSEQ / 32, LSEQ / 32, BATCH), dim3(32, 8)>>>(Eh, A2h, A1T);

    // merged apply: x2_out = A2 @ V2  |  x1_mid^T = (A1^T @ V1) * mask
    apply_dual_k<<<dim3(8, 16, 16), blk, SMEM_TOTAL>>>(A2h, A1T, V2T, V1T, out2, XmT, mask);

    // x1_out = A2 @ x1_mid
    final_k<<<dim3(8, 16, 8), blk, SMEM_TOTAL>>>(A2h, XmT, out1);
}

// round 11
// speedup vs baseline: 3.5687x; 1.0383x over previous
#include <cuda_runtime.h>
#include <cuda_fp16.h>
#include <math.h>
#include <stdint.h>

// Problem constants
#define BATCH 8
#define LSEQ  2048
#define DDIM  1024
#define NEGF  (-1e30f)

// GEMM tiling: CTA 128(M) x 128(N) x 64(K halves), 8 warps as 2(m) x 4(n), warp tile 64x32
// 2 CTAs per SM (regs capped to 128, smem 110.6KB/CTA)
#define NTHREADS 256
#define STAGES 3
#define ROW_BYTES 144                       // 64 halves (128B) + 16B pad
#define A_BYTES (128 * ROW_BYTES)           // 18432
#define B_BYTES (128 * ROW_BYTES)           // 18432
#define STAGE_BYTES (A_BYTES + B_BYTES)     // 36864
#define SMEM_TOTAL (STAGES * STAGE_BYTES)   // 110592

// ---------------- scratch (device globals; no allocation allowed) ----------------
__device__ __half g_Qh [(size_t)BATCH * LSEQ * DDIM];
__device__ __half g_Kh [(size_t)BATCH * LSEQ * DDIM];
__device__ __half g_V1T[(size_t)BATCH * DDIM * LSEQ];
__device__ __half g_V2T[(size_t)BATCH * DDIM * LSEQ];
__device__ __half g_XmT[(size_t)BATCH * DDIM * LSEQ];
__device__ __half g_Eh [(size_t)BATCH * LSEQ * LSEQ];   // exp(logits) [l,m], half
__device__ __half g_ETh[(size_t)BATCH * LSEQ * LSEQ];   // exp(logits)^T [m,l], half
__device__ float  g_rowsum[BATCH * LSEQ];
__device__ float  g_colsum[BATCH * LSEQ];
__device__ __half g_x1h[(size_t)BATCH * LSEQ * DDIM];
__device__ __half g_x2h[(size_t)BATCH * LSEQ * DDIM];
__device__ __half g_Wqh[(size_t)DDIM * DDIM];
__device__ __half g_Wkh[(size_t)DDIM * DDIM];
__device__ __half g_Wvh[(size_t)DDIM * DDIM];

// ---------------- helpers ----------------
__device__ __forceinline__ uint32_t smem_to_u32(const void* p) {
    uint32_t a;
    asm("{ .reg .u64 t; cvta.to.shared.u64 t, %1; cvt.u32.u64 %0, t; }" : "=r"(a) : "l"(p));
    return a;
}

#define CP_ASYNC16(dst, src) \
    asm volatile("cp.async.cg.shared.global [%0], [%1], 16;" :: "r"(dst), "l"(src) : "memory")
#define CP_COMMIT() asm volatile("cp.async.commit_group;" ::: "memory")

#define LDSM_X4(r, addr) \
    asm volatile("ldmatrix.sync.aligned.m8n8.x4.shared.b16 {%0,%1,%2,%3}, [%4];" \
        : "=r"((r)[0]), "=r"((r)[1]), "=r"((r)[2]), "=r"((r)[3]) : "r"(addr))

// m16n8k16 fp16 MMA, fp32 accumulate
#define MMA_F16(d, a, b)                                                   \
    asm volatile(                                                          \
        "mma.sync.aligned.m16n8k16.row.col.f32.f16.f16.f32 "               \
        "{%0,%1,%2,%3}, {%4,%5,%6,%7}, {%8,%9}, {%0,%1,%2,%3};"            \
        : "+f"(d[0]), "+f"(d[1]), "+f"(d[2]), "+f"(d[3])                   \
        : "r"(a[0]), "r"(a[1]), "r"(a[2]), "r"(a[3]), "r"(b[0]), "r"(b[1]))

// ---------------------------------------------------------------------------
// NT GEMM body: C[m,n] = sum_k A[m,k]*B[n,k]; A,B __half [rows, K] k-contig.
// CTA tile 128x128x64. Warp tile 64x32.
// MODE 0: +bias[n], HALF out, normal store
// MODE 1: +bias[n], HALF out, transposed store C[n,m]
// MODE 2: e=__expf(acc*scale+(1-mask[z,n])*NEG); HALF dual store (normal Cv[m,n]
//         + transposed Cv2[n,m]) + atomic row/col sums
// MODE 3: FLOAT out, normal store, rows scaled by rcp(bias[z*M+m])  (bias = rowsum)
// MODE 4: HALF out, transposed store, rows scaled by mask[z,m]*rcp(bias[z*M+m]) (bias = colsum)
// ---------------------------------------------------------------------------
template <int MODE>
__device__ __forceinline__
void gemm_body(const __half* __restrict__ A, const __half* __restrict__ B,
               void* __restrict__ Cv, void* __restrict__ Cv2,
               int M, int N, int K, long long sA, long long sB, long long sC,
               const float* __restrict__ bias, const float* __restrict__ mask, float scale,
               int z, int m0, int n0, char* smc)
{
    const uint32_t smem_u = smem_to_u32(smc);
    const int tid = threadIdx.x, wid = tid >> 5, lane = tid & 31;
    const int wm = wid & 1, wn = wid >> 1;      // 2 x 4 warps, warp tile 64(m) x 32(n)
    const int g = lane >> 2, tg = lane & 3;

    const __half* Abase = A + (long long)z * sA + (long long)m0 * K;
    const __half* Bbase = B + (long long)z * sB + (long long)n0 * K;
    const int T = K >> 6;                       // 64 halves per k-tile

    // cp.async staging: 128 rows A + 128 rows B, rows of 64 halves = 128B = 8 chunks of 16B
    const int sr = tid >> 3;                    // 0..31
    const int sj = tid & 7;                     // chunk 0..7
    auto stage = [&](int u) {
        const int s = u % STAGES;
        const uint32_t sa = smem_u + s * STAGE_BYTES;
        const uint32_t sb = sa + A_BYTES;
        const __half* Asrc = Abase + (size_t)u * 64 + sj * 8;
        const __half* Bsrc = Bbase + (size_t)u * 64 + sj * 8;
        const uint32_t dw = sj * 16;
#pragma unroll
        for (int i = 0; i < 4; ++i) {
            const int r = sr + i * 32;
            CP_ASYNC16(sa + r * ROW_BYTES + dw, Asrc + (size_t)r * K);
        }
#pragma unroll
        for (int i = 0; i < 4; ++i) {
            const int r = sr + i * 32;
            CP_ASYNC16(sb + r * ROW_BYTES + dw, Bsrc + (size_t)r * K);
        }
        CP_COMMIT();
    };

    float acc[4][4][4];
#pragma unroll
    for (int a = 0; a < 4; ++a)
#pragma unroll
        for (int b = 0; b < 4; ++b)
#pragma unroll
            for (int c = 0; c < 4; ++c) acc[a][b][c] = 0.0f;

    stage(0);
    stage(1);

    // ldmatrix per-thread address offsets (bytes)
    const uint32_t a_lm = (uint32_t)((wm * 64 + (lane & 15)) * ROW_BYTES + (lane >> 4) * 16);
    const uint32_t b_lm = (uint32_t)((wn * 32 + ((lane >> 4) << 3) + (lane & 7)) * ROW_BYTES +
                                     ((lane >> 3) & 1) * 16);

    for (int t = 0; t < T; ++t) {
        if (t < T - 1) asm volatile("cp.async.wait_group 1;" ::: "memory");
        else           asm volatile("cp.async.wait_group 0;" ::: "memory");
        __syncthreads();

        if (t + 2 < T) stage(t + 2);

        const uint32_t sbase = smem_u + (t % STAGES) * STAGE_BYTES;
#pragma unroll
        for (int ks = 0; ks < 4; ++ks) {        // 4 k16 steps per 64-half tile
            const uint32_t abase = sbase + a_lm + ks * 32;
            const uint32_t bbase = sbase + A_BYTES + b_lm + ks * 32;
            uint32_t af[4][4], bf[2][4];
#pragma unroll
            for (int mt = 0; mt < 4; ++mt) LDSM_X4(af[mt], abase + mt * (16 * ROW_BYTES));
#pragma unroll
            for (int np = 0; np < 2; ++np) LDSM_X4(bf[np], bbase + np * (16 * ROW_BYTES));
#pragma unroll
            for (int mt = 0; mt < 4; ++mt)
#pragma unroll
                for (int nt = 0; nt < 4; ++nt)
                    MMA_F16(acc[mt][nt], af[mt], (bf[nt >> 1] + (nt & 1) * 2));
        }
    }

    // ---------------- epilogue ----------------
    if (MODE == 0) {
        __half* Cb = (__half*)Cv + (long long)z * sC;
#pragma unroll
        for (int mt = 0; mt < 4; ++mt)
#pragma unroll
            for (int nt = 0; nt < 4; ++nt) {
                const int mA = m0 + wm * 64 + mt * 16 + g;
                const int n  = n0 + wn * 32 + nt * 8 + tg * 2;
                const float b0 = bias[n], b1 = bias[n + 1];
                *(__half2*)(Cb + (long long)mA * N + n) =
                    __floats2half2_rn(acc[mt][nt][0] + b0, acc[mt][nt][1] + b1);
                *(__half2*)(Cb + (long long)(mA + 8) * N + n) =
                    __floats2half2_rn(acc[mt][nt][2] + b0, acc[mt][nt][3] + b1);
            }
    } else if (MODE == 2) {
        // exp in place, normal half store, atomic sums, then transposed half store
        __half* Cb  = (__half*)Cv  + (long long)z * sC;
        __half* Cb2 = (__half*)Cv2 + (long long)z * sC;
        float rs[8], cs[8];
#pragma unroll
        for (int i = 0; i < 8; ++i) { rs[i] = 0.0f; cs[i] = 0.0f; }
#pragma unroll
        for (int mt = 0; mt < 4; ++mt)
#pragma unroll
            for (int nt = 0; nt < 4; ++nt) {
                const int mA = m0 + wm * 64 + mt * 16 + g;
                const int n  = n0 + wn * 32 + nt * 8 + tg * 2;
                const float mb0 = (1.0f - mask[(long long)z * N + n]) * NEGF;
                const float mb1 = (1.0f - mask[(long long)z * N + n + 1]) * NEGF;
                const float e0 = __expf(acc[mt][nt][0] * scale + mb0);
                const float e1 = __expf(acc[mt][nt][1] * scale + mb1);
                const float e2 = __expf(acc[mt][nt][2] * scale + mb0);
                const float e3 = __expf(acc[mt][nt][3] * scale + mb1);
                acc[mt][nt][0] = e0; acc[mt][nt][1] = e1;
                acc[mt][nt][2] = e2; acc[mt][nt][3] = e3;
                *(__half2*)(Cb + (long long)mA * N + n)       = __floats2half2_rn(e0, e1);
                *(__half2*)(Cb + (long long)(mA + 8) * N + n) = __floats2half2_rn(e2, e3);
                rs[mt * 2]     += e0 + e1;
                rs[mt * 2 + 1] += e2 + e3;
                cs[nt * 2]     += e0 + e2;
                cs[nt * 2 + 1] += e1 + e3;
            }
        // row sums: reduce over tg (lane bits 0-1)
#pragma unroll
        for (int i = 0; i < 8; ++i) {
            rs[i] += __shfl_xor_sync(0xffffffffu, rs[i], 1);
            rs[i] += __shfl_xor_sync(0xffffffffu, rs[i], 2);
        }
        if (tg == 0) {
#pragma unroll
            for (int mt = 0; mt < 4; ++mt) {
                atomicAdd(&g_rowsum[z * LSEQ + m0 + wm * 64 + mt * 16 + g],     rs[mt * 2]);
                atomicAdd(&g_rowsum[z * LSEQ + m0 + wm * 64 + mt * 16 + g + 8], rs[mt * 2 + 1]);
            }
        }
        // col sums: reduce over g (lane bits 2-4)
#pragma unroll
        for (int i = 0; i < 8; ++i) {
            cs[i] += __shfl_xor_sync(0xffffffffu, cs[i], 4);
            cs[i] += __shfl_xor_sync(0xffffffffu, cs[i], 8);
            cs[i] += __shfl_xor_sync(0xffffffffu, cs[i], 16);
        }
        if (g == 0) {
#pragma unroll
            for (int nt = 0; nt < 4; ++nt) {
                atomicAdd(&g_colsum[z * LSEQ + n0 + wn * 32 + nt * 8 + tg * 2],     cs[nt * 2]);
                atomicAdd(&g_colsum[z * LSEQ + n0 + wn * 32 + nt * 8 + tg * 2 + 1], cs[nt * 2 + 1]);
            }
        }
        // transposed store of e: ET[n, m]
        {
            float* Csh = (float*)smc;   // [128][33]
#pragma unroll 1
            for (int ch = 0; ch < 4; ++ch) {
                __syncthreads();
                if (wn == ch) {
#pragma unroll
                    for (int mt = 0; mt < 4; ++mt)
#pragma unroll
                        for (int nt = 0; nt < 4; ++nt) {
                            const int ml = wm * 64 + mt * 16 + g;
                            const int nl = nt * 8 + tg * 2;
                            Csh[ml * 33 + nl]           = acc[mt][nt][0];
                            Csh[ml * 33 + nl + 1]       = acc[mt][nt][1];
                            Csh[(ml + 8) * 33 + nl]     = acc[mt][nt][2];
                            Csh[(ml + 8) * 33 + nl + 1] = acc[mt][nt][3];
                        }
                }
                __syncthreads();
#pragma unroll
                for (int i = 0; i < 16; ++i) {
                    const int idx = tid + i * 256;
                    const int nl = idx >> 7, m = idx & 127;
                    Cb2[(long long)(n0 + ch * 32 + nl) * M + m0 + m] =
                        __float2half_rn(Csh[m * 33 + nl]);
                }
            }
        }
    } else if (MODE == 3) {
        // float out, rows scaled by rcp(rowsum)
        float* Cb = (float*)Cv + (long long)z * sC;
#pragma unroll
        for (int mt = 0; mt < 4; ++mt) {
            const int mA = m0 + wm * 64 + mt * 16 + g;
            const float r0v = bias[z * M + mA];
            const float r1v = bias[z * M + mA + 8];
            const float rr0 = r0v > 0.0f ? 1.0f / r0v : 0.0f;
            const float rr1 = r1v > 0.0f ? 1.0f / r1v : 0.0f;
#pragma unroll
            for (int nt = 0; nt < 4; ++nt) {
                const int n = n0 + wn * 32 + nt * 8 + tg * 2;
                *(float2*)(Cb + (long long)mA * N + n) =
                    make_float2(acc[mt][nt][0] * rr0, acc[mt][nt][1] * rr0);
                *(float2*)(Cb + (long long)(mA + 8) * N + n) =
                    make_float2(acc[mt][nt][2] * rr1, acc[mt][nt][3] * rr1);
            }
        }
    } else {
        // MODE 1 / MODE 4: transposed HALF store via smem staging, four 32-col chunks
        float* Csh = (float*)smc;   // [128][33]
        __half* Cb = (__half*)Cv + (long long)z * sC;
#pragma unroll 1
        for (int ch = 0; ch < 4; ++ch) {
            __syncthreads();
            if (wn == ch) {
#pragma unroll
                for (int mt = 0; mt < 4; ++mt) {
                    const int ml = wm * 64 + mt * 16 + g;
                    float f0 = 1.0f, f1 = 1.0f;
                    if (MODE == 4) {
                        const float c0 = bias[z * M + m0 + ml];
                        const float c1 = bias[z * M + m0 + ml + 8];
                        f0 = mask[(long long)z * M + m0 + ml]     * (c0 > 0.0f ? 1.0f / c0 : 0.0f);
                        f1 = mask[(long long)z * M + m0 + ml + 8] * (c1 > 0.0f ? 1.0f / c1 : 0.0f);
                    }
#pragma unroll
                    for (int nt = 0; nt < 4; ++nt) {
                        const int nl = nt * 8 + tg * 2;
                        float v0 = acc[mt][nt][0], v1 = acc[mt][nt][1];
                        float v2 = acc[mt][nt][2], v3 = acc[mt][nt][3];
                        if (MODE == 1) {
                            const float b0 = bias[n0 + ch * 32 + nl];
                            const float b1 = bias[n0 + ch * 32 + nl + 1];
                            v0 += b0; v1 += b1; v2 += b0; v3 += b1;
                        }
                        if (MODE == 4) {
                            v0 *= f0; v1 *= f0; v2 *= f1; v3 *= f1;
                        }
                        Csh[ml * 33 + nl]           = v0;
                        Csh[ml * 33 + nl + 1]       = v1;
                        Csh[(ml + 8) * 33 + nl]     = v2;
                        Csh[(ml + 8) * 33 + nl + 1] = v3;
                    }
                }
            }
            __syncthreads();
#pragma unroll
            for (int i = 0; i < 16; ++i) {
                const int idx = tid + i * 256;
                const int nl = idx >> 7, m = idx & 127;
                Cb[(long long)(n0 + ch * 32 + nl) * M + m0 + m] =
                    __float2half_rn(Csh[m * 33 + nl]);
            }
        }
    }
}

// ---------------- GEMM kernel wrappers ----------------
// All projections in one launch: z<8 -> x1 {Q, V1T}; z>=8 -> x2 {K, V2T}
__global__ __launch_bounds__(NTHREADS, 2)
void proj_all_k(const __half* __restrict__ x1h, const __half* __restrict__ x2h,
                const __half* __restrict__ Wqh, const __half* __restrict__ Wkh,
                const __half* __restrict__ Wvh,
                __half* __restrict__ Qh, __half* __restrict__ Kh,
                __half* __restrict__ V1T, __half* __restrict__ V2T,
                const float* __restrict__ bq, const float* __restrict__ bk,
                const float* __restrict__ bv)
{
    extern __shared__ char smc[];
    const int zz = blockIdx.z, m0 = blockIdx.y * 128, bx = blockIdx.x;
    const long long sX = (long long)LSEQ * DDIM;
    const long long sT = (long long)DDIM * LSEQ;
    if (zz < 8) {
        if (bx < 8)
            gemm_body<0>(x1h, Wqh, Qh,  nullptr, LSEQ, DDIM, DDIM, sX, 0, sX, bq, nullptr, 0.f, zz, m0, bx * 128, smc);
        else
            gemm_body<1>(x1h, Wvh, V1T, nullptr, LSEQ, DDIM, DDIM, sX, 0, sT, bv, nullptr, 0.f, zz, m0, (bx - 8) * 128, smc);
    } else {
        const int z = zz - 8;
        if (bx < 8)
            gemm_body<0>(x2h, Wkh, Kh,  nullptr, LSEQ, DDIM, DDIM, sX, 0, sX, bk, nullptr, 0.f, z, m0, bx * 128, smc);
        else
            gemm_body<1>(x2h, Wvh, V2T, nullptr, LSEQ, DDIM, DDIM, sX, 0, sT, bv, nullptr, 0.f, z, m0, (bx - 8) * 128, smc);
    }
}

// Logits GEMM with fused exp + dual store (E, ET) + row/col sums
__global__ __launch_bounds__(NTHREADS, 2)
void sgemm_k(const __half* __restrict__ Q, const __half* __restrict__ Kh,
             __half* __restrict__ E, __half* __restrict__ ET,
             const float* __restrict__ mask, float scale)
{
    extern __shared__ char smc[];
    const long long sX = (long long)LSEQ * DDIM;
    const long long sS = (long long)LSEQ * LSEQ;
    gemm_body<2>(Q, Kh, E, ET, LSEQ, LSEQ, DDIM, sX, sX, sS, nullptr, mask, scale,
                 blockIdx.z, blockIdx.y * 128, blockIdx.x * 128, smc);
}

// merged apply: z<8: x2_out = (E @ V2) * rcp(rowsum)  |  z>=8: XmT = (ET @ V1) * mask*rcp(colsum)
__global__ __launch_bounds__(NTHREADS, 2)
void apply_dual_k(const __half* __restrict__ E, const __half* __restrict__ ET,
                  const __half* __restrict__ V2T, const __half* __restrict__ V1T,
                  float* __restrict__ out2, __half* __restrict__ XmT,
                  const float* __restrict__ rowsum, const float* __restrict__ colsum,
                  const float* __restrict__ mask)
{
    extern __shared__ char smc[];
    const int m0 = blockIdx.y * 128, n0 = blockIdx.x * 128;
    const long long sX = (long long)LSEQ * DDIM;
    const long long sT = (long long)DDIM * LSEQ;
    const long long sS = (long long)LSEQ * LSEQ;
    if (blockIdx.z < 8)
        gemm_body<3>(E, V2T, out2, nullptr, LSEQ, DDIM, LSEQ, sS, sT, sX, rowsum, nullptr, 0.f,
                     blockIdx.z, m0, n0, smc);
    else
        gemm_body<4>(ET, V1T, XmT, nullptr, LSEQ, DDIM, LSEQ, sS, sT, sT, colsum, mask, 0.f,
                     blockIdx.z - 8, m0, n0, smc);
}

// x1_out = (E @ x1_mid) * rcp(rowsum)
__global__ __launch_bounds__(NTHREADS, 2)
void final_k(const __half* __restrict__ E, const __half* __restrict__ XmT,
             float* __restrict__ out1, const float* __restrict__ rowsum)
{
    extern __shared__ char smc[];
    const long long sX = (long long)LSEQ * DDIM;
    const long long sT = (long long)DDIM * LSEQ;
    const long long sS = (long long)LSEQ * LSEQ;
    gemm_body<3>(E, XmT, out1, nullptr, LSEQ, DDIM, LSEQ, sS, sT, sX, rowsum, nullptr, 0.f,
                 blockIdx.z, blockIdx.y * 128, blockIdx.x * 128, smc);
}

// ---------------- merged fp32 -> fp16 conversion of all external GEMM inputs ----------------
#define NX4 (BATCH * LSEQ * DDIM / 4)   // 4194304
#define NW4 (DDIM * DDIM / 4)           // 262144
#define CVT_TOTAL (2 * NX4 + 3 * NW4)   // 9175040

__global__ __launch_bounds__(256)
void cvt_all_k(const float4* __restrict__ x1, const float4* __restrict__ x2,
               const float4* __restrict__ Wq, const float4* __restrict__ Wk,
               const float4* __restrict__ Wv,
               __half2* __restrict__ x1h, __half2* __restrict__ x2h,
               __half2* __restrict__ Wqh, __half2* __restrict__ Wkh,
               __half2* __restrict__ Wvh)
{
    int i = blockIdx.x * 256 + threadIdx.x;
    if (i >= CVT_TOTAL) return;
    const float4* src;
    __half2* dst;
    if (i < NX4)               { src = x1; dst = x1h; }
    else if (i < 2 * NX4)      { src = x2; dst = x2h; i -= NX4; }
    else if (i < 2 * NX4 + NW4)     { src = Wq; dst = Wqh; i -= 2 * NX4; }
    else if (i < 2 * NX4 + 2 * NW4) { src = Wk; dst = Wkh; i -= 2 * NX4 + NW4; }
    else                            { src = Wv; dst = Wvh; i -= 2 * NX4 + 2 * NW4; }
    const float4 v = src[i];
    dst[2 * i]     = __floats2half2_rn(v.x, v.y);
    dst[2 * i + 1] = __floats2half2_rn(v.z, v.w);
}

// ---------------- zero row/col sums ----------------
__global__ __launch_bounds__(256)
void zero2_k()
{
    const int i = blockIdx.x * 256 + threadIdx.x;
    if (i < BATCH * LSEQ) {
        g_rowsum[i] = 0.0f;
        g_colsum[i] = 0.0f;
    }
}

// ---------------- launcher ----------------
extern "C" void kernel_launch(void* const* d_in, const int* in_sizes, int n_in,
                              void* d_out, int out_size)
{
    const float* x1   = (const float*)d_in[0];
    const float* x2   = (const float*)d_in[1];
    const float* mask = (const float*)d_in[2];
    const float* Wq   = (const float*)d_in[3];
    const float* bq   = (const float*)d_in[4];
    const float* Wk   = (const float*)d_in[5];
    const float* bk   = (const float*)d_in[6];
    const float* Wv   = (const float*)d_in[7];
    const float* bv   = (const float*)d_in[8];

    float* out1 = (float*)d_out;
    float* out2 = out1 + (long long)BATCH * LSEQ * DDIM;

    __half *Qh, *Kh, *V1T, *V2T, *XmT, *Eh, *ETh, *x1h, *x2h, *Wqh, *Wkh, *Wvh;
    float *rowsum, *colsum;
    cudaGetSymbolAddress((void**)&Qh,     g_Qh);
    cudaGetSymbolAddress((void**)&Kh,     g_Kh);
    cudaGetSymbolAddress((void**)&V1T,    g_V1T);
    cudaGetSymbolAddress((void**)&V2T,    g_V2T);
    cudaGetSymbolAddress((void**)&XmT,    g_XmT);
    cudaGetSymbolAddress((void**)&Eh,     g_Eh);
    cudaGetSymbolAddress((void**)&ETh,    g_ETh);
    cudaGetSymbolAddress((void**)&rowsum, g_rowsum);
    cudaGetSymbolAddress((void**)&colsum, g_colsum);
    cudaGetSymbolAddress((void**)&x1h,    g_x1h);
    cudaGetSymbolAddress((void**)&x2h,    g_x2h);
    cudaGetSymbolAddress((void**)&Wqh,    g_Wqh);
    cudaGetSymbolAddress((void**)&Wkh,    g_Wkh);
    cudaGetSymbolAddress((void**)&Wvh,    g_Wvh);

    cudaFuncSetAttribute(proj_all_k,   cudaFuncAttributeMaxDynamicSharedMemorySize, SMEM_TOTAL);
    cudaFuncSetAttribute(sgemm_k,      cudaFuncAttributeMaxDynamicSharedMemorySize, SMEM_TOTAL);
    cudaFuncSetAttribute(apply_dual_k, cudaFuncAttributeMaxDynamicSharedMemorySize, SMEM_TOTAL);
    cudaFuncSetAttribute(final_k,      cudaFuncAttributeMaxDynamicSharedMemorySize, SMEM_TOTAL);

    const float scale = 0.03125f;  // 1/sqrt(1024)

    dim3 blk(NTHREADS);

    // convert all external inputs to fp16 (single launch) + zero sums
    cvt_all_k<<<(CVT_TOTAL + 255) / 256, 256>>>((const float4*)x1, (const float4*)x2,
                                                (const float4*)Wq, (const float4*)Wk,
                                                (const float4*)Wv,
                                                (__half2*)x1h, (__half2*)x2h,
                                                (__half2*)Wqh, (__half2*)Wkh, (__half2*)Wvh);
    zero2_k<<<(BATCH * LSEQ + 255) / 256, 256>>>();

    // all projections: x1 -> {Q, V1T}; x2 -> {K, V2T}
    proj_all_k<<<dim3(16, 16, 16), blk, SMEM_TOTAL>>>(x1h, x2h, Wqh, Wkh, Wvh,
                                                      Qh, Kh, V1T, V2T, bq, bk, bv);

    // logits GEMM: E = exp(QK^T*scale + maskbias), dual store (E, ET) + row/col sums
    sgemm_k<<<dim3(16, 16, 8), blk, SMEM_TOTAL>>>(Qh, Kh, Eh, ETh, mask, scale);

    // merged apply: x2_out = (E@V2)/rowsum  |  XmT = (ET@V1)*mask/colsum
    apply_dual_k<<<dim3(8, 16, 16), blk, SMEM_TOTAL>>>(Eh, ETh, V2T, V1T, out2, XmT,
                                                       rowsum, colsum, mask);

    // x1_out = (E @ x1_mid)/rowsum
    final_k<<<dim3(8, 16, 8), blk, SMEM_TOTAL>>>(Eh, XmT, out1, rowsum);
}